// round 5
// baseline (speedup 1.0000x reference)
#include <cuda_runtime.h>
#include <math.h>

#define BB 16
#define NN 4096
#define CC 64
#define PP 1024
#define SS 32
#define NROWS (BB*PP*SS)   // 524288

__device__ float  d_featT[(size_t)BB*NN*CC];
__device__ float  d_newxyz[BB*PP*3];
__device__ int    d_idx[BB*PP*SS];
__device__ float  d_h1[(size_t)NROWS*68];
__device__ float  d_y1[(size_t)NROWS*64];
__device__ float  d_y2[(size_t)NROWS*64];
__device__ float  d_y3[(size_t)NROWS*128];
__device__ float  d_m3[(size_t)BB*PP*128];
__device__ double g_s1[64], g_q1[64], g_s2[64], g_q2[64], g_s3[128], g_q3[128];
__device__ float  g_a1[64], g_c1[64], g_a2[64], g_c2[64], g_a3[128], g_c3[128];

__device__ __forceinline__ float sqdist(float ax,float ay,float az,float bx,float by,float bz){
    float dx=__fsub_rn(ax,bx), dy=__fsub_rn(ay,by), dz=__fsub_rn(az,bz);
    return __fadd_rn(__fadd_rn(__fmul_rn(dx,dx),__fmul_rn(dy,dy)),__fmul_rn(dz,dz));
}

__global__ void zero_stats(){
    int t=threadIdx.x;
    if(t<64){g_s1[t]=0.0;g_q1[t]=0.0;g_s2[t]=0.0;g_q2[t]=0.0;}
    if(t<128){g_s3[t]=0.0;g_q3[t]=0.0;}
}

__global__ void transpose_feat(const float* __restrict__ f){
    __shared__ float t[32][33];
    int b=blockIdx.z, c0=blockIdx.y*32, n0=blockIdx.x*32;
    const float* src=f+((size_t)b*CC+c0)*NN+n0;
#pragma unroll
    for(int k=0;k<32;k+=8)
        t[threadIdx.y+k][threadIdx.x]=src[(size_t)(threadIdx.y+k)*NN+threadIdx.x];
    __syncthreads();
    float* dst=d_featT+((size_t)b*NN+n0)*CC+c0;
#pragma unroll
    for(int k=0;k<32;k+=8)
        dst[(size_t)(threadIdx.y+k)*CC+threadIdx.x]=t[threadIdx.x][threadIdx.y+k];
}

__global__ __launch_bounds__(1024,1) void fps_kernel(const float* __restrict__ xyz,
                                                     float* __restrict__ out_newxyz){
    int b=blockIdx.x, tid=threadIdx.x;
    const float* X=xyz+(size_t)b*NN*3;
    float px[4],py[4],pz[4],dd[4];
#pragma unroll
    for(int j=0;j<4;j++){
        int p=tid+j*1024;
        px[j]=X[p*3+0]; py[j]=X[p*3+1]; pz[j]=X[p*3+2]; dd[j]=1e10f;
    }
    __shared__ float s_last[3];
    __shared__ unsigned long long s_red[33];
    if(tid==0){
        s_last[0]=px[0]; s_last[1]=py[0]; s_last[2]=pz[0];
        float* o1=d_newxyz+(size_t)b*PP*3; o1[0]=px[0];o1[1]=py[0];o1[2]=pz[0];
        float* o2=out_newxyz+(size_t)b*PP*3; o2[0]=px[0];o2[1]=py[0];o2[2]=pz[0];
    }
    __syncthreads();
    for(int it=1; it<PP; it++){
        float lx=s_last[0], ly=s_last[1], lz=s_last[2];
        unsigned long long best=0ull;
#pragma unroll
        for(int j=0;j<4;j++){
            float d=sqdist(px[j],py[j],pz[j],lx,ly,lz);
            float nd=fminf(dd[j],d); dd[j]=nd;
            unsigned long long k=((unsigned long long)__float_as_uint(nd)<<32)
                               |(unsigned)(NN-1-(tid+j*1024));
            best=(k>best)?k:best;
        }
#pragma unroll
        for(int off=16;off>0;off>>=1){
            unsigned long long o=__shfl_down_sync(0xffffffffu,best,off);
            best=(o>best)?o:best;
        }
        if((tid&31)==0) s_red[tid>>5]=best;
        __syncthreads();
        if(tid<32){
            unsigned long long v=s_red[tid];
#pragma unroll
            for(int off=16;off>0;off>>=1){
                unsigned long long o=__shfl_down_sync(0xffffffffu,v,off);
                v=(o>v)?o:v;
            }
            if(tid==0) s_red[32]=v;
        }
        __syncthreads();
        unsigned long long win=s_red[32];
        int widx=(NN-1)-(int)(unsigned)(win&0xffffffffu);
        if((widx&1023)==tid){
            int j=widx>>10;
            s_last[0]=px[j]; s_last[1]=py[j]; s_last[2]=pz[j];
            float* o1=d_newxyz+((size_t)b*PP+it)*3; o1[0]=px[j];o1[1]=py[j];o1[2]=pz[j];
            float* o2=out_newxyz+((size_t)b*PP+it)*3; o2[0]=px[j];o2[1]=py[j];o2[2]=pz[j];
        }
        __syncthreads();
    }
}

__global__ __launch_bounds__(128) void ballq_kernel(const float* __restrict__ xyz){
    int warp=blockIdx.x*4+(threadIdx.x>>5);
    int lane=threadIdx.x&31;
    int b=warp>>10;
    const float* X=xyz+(size_t)b*NN*3;
    float cx=d_newxyz[warp*3+0], cy=d_newxyz[warp*3+1], cz=d_newxyz[warp*3+2];
    int* out=d_idx+(size_t)warp*SS;
    const float R2=0.04f;
    int cnt=0, firstIdx=-1;
    for(int base=0; base<NN && cnt<SS; base+=32){
        int n=base+lane;
        float x=X[n*3+0], y=X[n*3+1], z=X[n*3+2];
        bool in=sqdist(cx,cy,cz,x,y,z)<R2;
        unsigned m=__ballot_sync(0xffffffffu,in);
        if(firstIdx<0 && m) firstIdx=base+__ffs(m)-1;
        if(in){
            int pos=cnt+__popc(m&((1u<<lane)-1u));
            if(pos<SS) out[pos]=n;
        }
        cnt+=__popc(m);
    }
    int written=cnt<SS?cnt:SS;
    if(lane>=written) out[lane]=firstIdx;
}

// one warp per row: build H1 (row-major, stride 68: [dx,dy,dz, f0..f63, pad])
__global__ __launch_bounds__(256) void gather_h1(const float* __restrict__ xyz){
    int row=blockIdx.x*8+(threadIdx.x>>5);
    int lane=threadIdx.x&31;
    int grp=row>>5, s=row&31, b=grp>>10;
    int i=d_idx[(size_t)grp*SS+s];
    float* h=d_h1+(size_t)row*68;
    const float* fsrc=d_featT+((size_t)b*NN+i)*CC;
    h[3+lane]=fsrc[lane];
    h[35+lane]=fsrc[32+lane];
    if(lane<3)
        h[lane]=__fsub_rn(xyz[((size_t)b*NN+i)*3+lane], d_newxyz[(size_t)grp*3+lane]);
    if(lane==3) h[67]=0.f;
}

#define GEMM_BODY(Kc, SHX, SHW, ACC0, ACC1, R0, OG) \
_Pragma("unroll 4") \
for(int c=0;c<(Kc);c++){ \
    float h0=SHX[R0][c], h1=SHX[R0+1][c]; \
    const float4* wp=(const float4*)&SHW[c][(OG)*8]; \
    float4 wa=wp[0], wb=wp[1]; \
    ACC0[0]=fmaf(h0,wa.x,ACC0[0]); ACC1[0]=fmaf(h1,wa.x,ACC1[0]); \
    ACC0[1]=fmaf(h0,wa.y,ACC0[1]); ACC1[1]=fmaf(h1,wa.y,ACC1[1]); \
    ACC0[2]=fmaf(h0,wa.z,ACC0[2]); ACC1[2]=fmaf(h1,wa.z,ACC1[2]); \
    ACC0[3]=fmaf(h0,wa.w,ACC0[3]); ACC1[3]=fmaf(h1,wa.w,ACC1[3]); \
    ACC0[4]=fmaf(h0,wb.x,ACC0[4]); ACC1[4]=fmaf(h1,wb.x,ACC1[4]); \
    ACC0[5]=fmaf(h0,wb.y,ACC0[5]); ACC1[5]=fmaf(h1,wb.y,ACC1[5]); \
    ACC0[6]=fmaf(h0,wb.z,ACC0[6]); ACC1[6]=fmaf(h1,wb.z,ACC1[6]); \
    ACC0[7]=fmaf(h0,wb.w,ACC0[7]); ACC1[7]=fmaf(h1,wb.w,ACC1[7]); \
}

#define STORE2x8(DST, BASE, A0, A1, RS) \
    ((float4*)((DST)+(BASE)))[0]=make_float4(A0[0],A0[1],A0[2],A0[3]); \
    ((float4*)((DST)+(BASE)))[1]=make_float4(A0[4],A0[5],A0[6],A0[7]); \
    ((float4*)((DST)+(BASE)+(RS)))[0]=make_float4(A1[0],A1[1],A1[2],A1[3]); \
    ((float4*)((DST)+(BASE)+(RS)))[1]=make_float4(A1[4],A1[5],A1[6],A1[7]);

__global__ __launch_bounds__(256) void gemm_l1(const float* __restrict__ W1){
    __shared__ __align__(16) float sh_h[64][68];
    __shared__ __align__(16) float sh_w[67][68];
    int tid=threadIdx.x, blk=blockIdx.x;
    for(int e=tid;e<64*67;e+=256){ int o=e/67, c=e-o*67; sh_w[c][o]=W1[e]; }
    {
        int r=tid>>2, q=tid&3;
        const float4* src=(const float4*)(d_h1+((size_t)blk*64+r)*68);
        float4* dst=(float4*)&sh_h[r][0];
#pragma unroll
        for(int f=q; f<17; f+=4) dst[f]=src[f];
    }
    __syncthreads();
    int og=tid&7, sp=tid>>3, r0=sp*2;
    float acc0[8]={0,0,0,0,0,0,0,0}, acc1[8]={0,0,0,0,0,0,0,0};
    GEMM_BODY(67, sh_h, sh_w, acc0, acc1, r0, og)
    size_t base=((size_t)blk*64+r0)*64+og*8;
    STORE2x8(d_y1, base, acc0, acc1, 64)
}

__global__ __launch_bounds__(256) void gemm_l2(const float* __restrict__ W2){
    __shared__ __align__(16) float sh_x[64][68];
    __shared__ __align__(16) float sh_w[64][68];
    int tid=threadIdx.x, blk=blockIdx.x;
    for(int e=tid;e<64*64;e+=256){ int o=e>>6, c=e&63; sh_w[c][o]=W2[e]; }
    {
        int r=tid>>2, q=tid&3;
        const float4* src=(const float4*)(d_y1+((size_t)blk*64+r)*64+q*16);
#pragma unroll
        for(int k=0;k<4;k++){
            float4 v=src[k];
            int c0=q*16+k*4;
            sh_x[r][c0+0]=fmaxf(fmaf(g_a1[c0+0],v.x,g_c1[c0+0]),0.f);
            sh_x[r][c0+1]=fmaxf(fmaf(g_a1[c0+1],v.y,g_c1[c0+1]),0.f);
            sh_x[r][c0+2]=fmaxf(fmaf(g_a1[c0+2],v.z,g_c1[c0+2]),0.f);
            sh_x[r][c0+3]=fmaxf(fmaf(g_a1[c0+3],v.w,g_c1[c0+3]),0.f);
        }
    }
    __syncthreads();
    int og=tid&7, sp=tid>>3, r0=sp*2;
    float acc0[8]={0,0,0,0,0,0,0,0}, acc1[8]={0,0,0,0,0,0,0,0};
    GEMM_BODY(64, sh_x, sh_w, acc0, acc1, r0, og)
    size_t base=((size_t)blk*64+r0)*64+og*8;
    STORE2x8(d_y2, base, acc0, acc1, 64)
}

__global__ __launch_bounds__(256) void gemm_l3(const float* __restrict__ W3){
    __shared__ __align__(16) float sh_x[32][68];
    __shared__ __align__(16) float sh_w[64][132];
    int tid=threadIdx.x, blk=blockIdx.x;
    for(int e=tid;e<128*64;e+=256){ int o=e>>6, c=e&63; sh_w[c][o]=W3[e]; }
    {
        int r=tid>>3, q=tid&7;
        const float4* src=(const float4*)(d_y2+((size_t)blk*32+r)*64+q*8);
#pragma unroll
        for(int k=0;k<2;k++){
            float4 v=src[k];
            int c0=q*8+k*4;
            sh_x[r][c0+0]=fmaxf(fmaf(g_a2[c0+0],v.x,g_c2[c0+0]),0.f);
            sh_x[r][c0+1]=fmaxf(fmaf(g_a2[c0+1],v.y,g_c2[c0+1]),0.f);
            sh_x[r][c0+2]=fmaxf(fmaf(g_a2[c0+2],v.z,g_c2[c0+2]),0.f);
            sh_x[r][c0+3]=fmaxf(fmaf(g_a2[c0+3],v.w,g_c2[c0+3]),0.f);
        }
    }
    __syncthreads();
    int og=tid&15, sp=tid>>4, r0=sp*2;
    float acc0[8]={0,0,0,0,0,0,0,0}, acc1[8]={0,0,0,0,0,0,0,0};
    GEMM_BODY(64, sh_x, sh_w, acc0, acc1, r0, og)
    size_t base=((size_t)blk*32+r0)*128+og*8;
    STORE2x8(d_y3, base, acc0, acc1, 128)
}

__global__ __launch_bounds__(256) void stats_kernel(int layer){
    const float* y; size_t total; int Cm; double *s, *q;
    if(layer==1){ y=d_y1; total=(size_t)NROWS*64; Cm=63; s=g_s1; q=g_q1; }
    else if(layer==2){ y=d_y2; total=(size_t)NROWS*64; Cm=63; s=g_s2; q=g_q2; }
    else { y=d_y3; total=(size_t)NROWS*128; Cm=127; s=g_s3; q=g_q3; }
    size_t stride=(size_t)gridDim.x*blockDim.x;
    size_t i=(size_t)blockIdx.x*blockDim.x+threadIdx.x;
    int c=(int)(i&(size_t)Cm);
    double ls=0.0, lq=0.0;
    for(; i<total; i+=stride){ double v=(double)y[i]; ls+=v; lq+=v*v; }
    atomicAdd(&s[c], ls);
    atomicAdd(&q[c], lq);
}

__global__ void mkscale_kernel(const float* __restrict__ g, const float* __restrict__ bb,
                               int layer, int Cn){
    int o=threadIdx.x;
    if(o>=Cn) return;
    const double inv=1.0/(double)NROWS;
    double s,q;
    if(layer==1){s=g_s1[o];q=g_q1[o];}
    else if(layer==2){s=g_s2[o];q=g_q2[o];}
    else {s=g_s3[o];q=g_q3[o];}
    double m=s*inv, v=q*inv-m*m;
    double aa=(double)g[o]/sqrt(v+1e-5);
    float af=(float)aa, cf=(float)((double)bb[o]-m*aa);
    if(layer==1){g_a1[o]=af;g_c1[o]=cf;}
    else if(layer==2){g_a2[o]=af;g_c2[o]=cf;}
    else {g_a3[o]=af;g_c3[o]=cf;}
}

__global__ __launch_bounds__(128) void maxpool_kernel(){
    int grp=blockIdx.x, o=threadIdx.x;
    const float* p=d_y3+(size_t)grp*SS*128+o;
    float m=p[0];
#pragma unroll
    for(int s=1;s<SS;s++) m=fmaxf(m,p[(size_t)s*128]);
    d_m3[(size_t)grp*128+o]=m;
}

__global__ void final_kernel(float* __restrict__ outf){
    __shared__ float t[32][33];
    int b=blockIdx.z, o0=blockIdx.y*32, p0=blockIdx.x*32;
#pragma unroll
    for(int k=0;k<32;k+=8){
        int p=p0+threadIdx.y+k, o=o0+threadIdx.x;
        float v=d_m3[((size_t)b*PP+p)*128+o];
        t[threadIdx.y+k][threadIdx.x]=fmaxf(fmaf(g_a3[o],v,g_c3[o]),0.f);
    }
    __syncthreads();
#pragma unroll
    for(int k=0;k<32;k+=8){
        int o=o0+threadIdx.y+k;
        outf[((size_t)b*128+o)*PP+p0+threadIdx.x]=t[threadIdx.x][threadIdx.y+k];
    }
}

extern "C" void kernel_launch(void* const* d_in, const int* in_sizes, int n_in,
                              void* d_out, int out_size){
    const float* xyz =(const float*)d_in[0];
    const float* feat=(const float*)d_in[1];
    const float* W1  =(const float*)d_in[2];
    const float* g1  =(const float*)d_in[3];
    const float* b1  =(const float*)d_in[4];
    const float* W2  =(const float*)d_in[5];
    const float* g2  =(const float*)d_in[6];
    const float* b2  =(const float*)d_in[7];
    const float* W3  =(const float*)d_in[8];
    const float* g3  =(const float*)d_in[9];
    const float* b3  =(const float*)d_in[10];
    float* out=(float*)d_out;
    float* out_newxyz=out;
    float* out_feat  =out+(size_t)BB*PP*3;

    zero_stats<<<1,128>>>();
    {
        dim3 g(NN/32, CC/32, BB), b(32,8);
        transpose_feat<<<g,b>>>(feat);
    }
    fps_kernel<<<BB,1024>>>(xyz, out_newxyz);
    ballq_kernel<<<(BB*PP)/4,128>>>(xyz);
    gather_h1<<<NROWS/8,256>>>(xyz);
    gemm_l1<<<NROWS/64,256>>>(W1);
    stats_kernel<<<128,256>>>(1);
    mkscale_kernel<<<1,128>>>(g1,b1,1,64);
    gemm_l2<<<NROWS/64,256>>>(W2);
    stats_kernel<<<128,256>>>(2);
    mkscale_kernel<<<1,128>>>(g2,b2,2,64);
    gemm_l3<<<NROWS/32,256>>>(W3);
    stats_kernel<<<128,256>>>(3);
    mkscale_kernel<<<1,128>>>(g3,b3,3,128);
    maxpool_kernel<<<BB*PP,128>>>();
    {
        dim3 g(PP/32, 128/32, BB), b(32,8);
        final_kernel<<<g,b>>>(out_feat);
    }
}

// round 6
// speedup vs baseline: 1.3951x; 1.3951x over previous
#include <cuda_runtime.h>
#include <math.h>

#define BB 16
#define NN 4096
#define CC 64
#define PP 1024
#define SS 32
#define NROWS (BB*PP*SS)   // 524288

__device__ float  d_featT[(size_t)BB*NN*CC];
__device__ float  d_xyzT[(size_t)BB*3*NN];
__device__ float  d_newxyz[BB*PP*3];
__device__ int    d_idx[BB*PP*SS];
__device__ float  d_y1[(size_t)NROWS*64];
__device__ float  d_y2[(size_t)NROWS*64];
__device__ float  d_m3[(size_t)BB*PP*128];
__device__ double g_s1[64], g_q1[64], g_s2[64], g_q2[64], g_s3[128], g_q3[128];
__device__ float  g_a1[64], g_c1[64], g_a2[64], g_c2[64], g_a3[128], g_c3[128];

__device__ __forceinline__ float sqdist(float ax,float ay,float az,float bx,float by,float bz){
    float dx=__fsub_rn(ax,bx), dy=__fsub_rn(ay,by), dz=__fsub_rn(az,bz);
    return __fadd_rn(__fadd_rn(__fmul_rn(dx,dx),__fmul_rn(dy,dy)),__fmul_rn(dz,dz));
}
__device__ __forceinline__ unsigned fkey(float f){
    unsigned u=__float_as_uint(f); return (u&0x80000000u)?~u:(u|0x80000000u);
}
__device__ __forceinline__ float finv(unsigned k){
    unsigned u=(k&0x80000000u)?(k&0x7fffffffu):~k; return __uint_as_float(u);
}

__global__ void zero_stats(){
    int t=threadIdx.x;
    if(t<64){g_s1[t]=0.0;g_q1[t]=0.0;g_s2[t]=0.0;g_q2[t]=0.0;}
    if(t<128){g_s3[t]=0.0;g_q3[t]=0.0;}
}

__global__ void transpose_feat(const float* __restrict__ f){
    __shared__ float t[32][33];
    int b=blockIdx.z, c0=blockIdx.y*32, n0=blockIdx.x*32;
    const float* src=f+((size_t)b*CC+c0)*NN+n0;
#pragma unroll
    for(int k=0;k<32;k+=8)
        t[threadIdx.y+k][threadIdx.x]=src[(size_t)(threadIdx.y+k)*NN+threadIdx.x];
    __syncthreads();
    float* dst=d_featT+((size_t)b*NN+n0)*CC+c0;
#pragma unroll
    for(int k=0;k<32;k+=8)
        dst[(size_t)(threadIdx.y+k)*CC+threadIdx.x]=t[threadIdx.x][threadIdx.y+k];
}

// xyz (B,N,3) -> planar (B,3,N)
__global__ __launch_bounds__(256) void xyz_soa(const float* __restrict__ xyz){
    __shared__ float s[768];
    int b=blockIdx.y, n0=blockIdx.x*256;
    const float* src=xyz+((size_t)b*NN+n0)*3;
    for(int k=threadIdx.x;k<768;k+=256) s[k]=src[k];
    __syncthreads();
    float* dst=d_xyzT+(size_t)b*3*NN;
    int n=n0+threadIdx.x;
    dst[n]        =s[threadIdx.x*3+0];
    dst[NN+n]     =s[threadIdx.x*3+1];
    dst[2*NN+n]   =s[threadIdx.x*3+2];
}

__global__ __launch_bounds__(1024,1) void fps_kernel(const float* __restrict__ xyz,
                                                     float* __restrict__ out_newxyz){
    int b=blockIdx.x, tid=threadIdx.x;
    const float* X=xyz+(size_t)b*NN*3;
    float px[4],py[4],pz[4],dd[4];
#pragma unroll
    for(int j=0;j<4;j++){
        int p=tid+j*1024;
        px[j]=X[p*3+0]; py[j]=X[p*3+1]; pz[j]=X[p*3+2]; dd[j]=1e10f;
    }
    __shared__ float s_last[3];
    __shared__ unsigned long long s_red[33];
    if(tid==0){
        s_last[0]=px[0]; s_last[1]=py[0]; s_last[2]=pz[0];
        float* o1=d_newxyz+(size_t)b*PP*3; o1[0]=px[0];o1[1]=py[0];o1[2]=pz[0];
        float* o2=out_newxyz+(size_t)b*PP*3; o2[0]=px[0];o2[1]=py[0];o2[2]=pz[0];
    }
    __syncthreads();
    for(int it=1; it<PP; it++){
        float lx=s_last[0], ly=s_last[1], lz=s_last[2];
        unsigned long long best=0ull;
#pragma unroll
        for(int j=0;j<4;j++){
            float d=sqdist(px[j],py[j],pz[j],lx,ly,lz);
            float nd=fminf(dd[j],d); dd[j]=nd;
            unsigned long long k=((unsigned long long)__float_as_uint(nd)<<32)
                               |(unsigned)(NN-1-(tid+j*1024));
            best=(k>best)?k:best;
        }
#pragma unroll
        for(int off=16;off>0;off>>=1){
            unsigned long long o=__shfl_down_sync(0xffffffffu,best,off);
            best=(o>best)?o:best;
        }
        if((tid&31)==0) s_red[tid>>5]=best;
        __syncthreads();
        if(tid<32){
            unsigned long long v=s_red[tid];
#pragma unroll
            for(int off=16;off>0;off>>=1){
                unsigned long long o=__shfl_down_sync(0xffffffffu,v,off);
                v=(o>v)?o:v;
            }
            if(tid==0) s_red[32]=v;
        }
        __syncthreads();
        unsigned long long win=s_red[32];
        int widx=(NN-1)-(int)(unsigned)(win&0xffffffffu);
        if((widx&1023)==tid){
            int j=widx>>10;
            s_last[0]=px[j]; s_last[1]=py[j]; s_last[2]=pz[j];
            float* o1=d_newxyz+((size_t)b*PP+it)*3; o1[0]=px[j];o1[1]=py[j];o1[2]=pz[j];
            float* o2=out_newxyz+((size_t)b*PP+it)*3; o2[0]=px[j];o2[1]=py[j];o2[2]=pz[j];
        }
        __syncthreads();
    }
}

__global__ __launch_bounds__(128) void ballq_kernel(){
    int warp=blockIdx.x*4+(threadIdx.x>>5);
    int lane=threadIdx.x&31;
    int b=warp>>10;
    const float* Xx=d_xyzT+(size_t)b*3*NN;
    const float* Xy=Xx+NN;
    const float* Xz=Xx+2*NN;
    float cx=d_newxyz[warp*3+0], cy=d_newxyz[warp*3+1], cz=d_newxyz[warp*3+2];
    int* out=d_idx+(size_t)warp*SS;
    const float R2=0.04f;
    int cnt=0, firstIdx=-1;
    for(int base=0; base<NN && cnt<SS; base+=32){
        int n=base+lane;
        bool in=sqdist(cx,cy,cz,Xx[n],Xy[n],Xz[n])<R2;
        unsigned m=__ballot_sync(0xffffffffu,in);
        if(firstIdx<0 && m) firstIdx=base+__ffs(m)-1;
        if(in){
            int pos=cnt+__popc(m&((1u<<lane)-1u));
            if(pos<SS) out[pos]=n;
        }
        cnt+=__popc(m);
    }
    int written=cnt<SS?cnt:SS;
    if(lane>=written) out[lane]=firstIdx;
}

#define GEMM_BODY(Kc, SHX, SHW, ACC0, ACC1, R0, OG) \
_Pragma("unroll 4") \
for(int c=0;c<(Kc);c++){ \
    float h0=SHX[R0][c], h1=SHX[R0+1][c]; \
    const float4* wp=(const float4*)&SHW[c][(OG)*8]; \
    float4 wa=wp[0], wb=wp[1]; \
    ACC0[0]=fmaf(h0,wa.x,ACC0[0]); ACC1[0]=fmaf(h1,wa.x,ACC1[0]); \
    ACC0[1]=fmaf(h0,wa.y,ACC0[1]); ACC1[1]=fmaf(h1,wa.y,ACC1[1]); \
    ACC0[2]=fmaf(h0,wa.z,ACC0[2]); ACC1[2]=fmaf(h1,wa.z,ACC1[2]); \
    ACC0[3]=fmaf(h0,wa.w,ACC0[3]); ACC1[3]=fmaf(h1,wa.w,ACC1[3]); \
    ACC0[4]=fmaf(h0,wb.x,ACC0[4]); ACC1[4]=fmaf(h1,wb.x,ACC1[4]); \
    ACC0[5]=fmaf(h0,wb.y,ACC0[5]); ACC1[5]=fmaf(h1,wb.y,ACC1[5]); \
    ACC0[6]=fmaf(h0,wb.z,ACC0[6]); ACC1[6]=fmaf(h1,wb.z,ACC1[6]); \
    ACC0[7]=fmaf(h0,wb.w,ACC0[7]); ACC1[7]=fmaf(h1,wb.w,ACC1[7]); \
}

#define STORE2x8(DST, BASE, A0, A1, RS) \
    ((float4*)((DST)+(BASE)))[0]=make_float4(A0[0],A0[1],A0[2],A0[3]); \
    ((float4*)((DST)+(BASE)))[1]=make_float4(A0[4],A0[5],A0[6],A0[7]); \
    ((float4*)((DST)+(BASE)+(RS)))[0]=make_float4(A1[0],A1[1],A1[2],A1[3]); \
    ((float4*)((DST)+(BASE)+(RS)))[1]=make_float4(A1[4],A1[5],A1[6],A1[7]);

// butterfly stats reduction over the 4 row-pair slots within a warp (lane bits 3,4)
#define STATS_RED_64(TS,TQ) \
_Pragma("unroll") \
for(int j=0;j<8;j++){ \
    TS[j]+=__shfl_xor_sync(0xffffffffu,TS[j],8); \
    TQ[j]+=__shfl_xor_sync(0xffffffffu,TQ[j],8); \
    TS[j]+=__shfl_xor_sync(0xffffffffu,TS[j],16); \
    TQ[j]+=__shfl_xor_sync(0xffffffffu,TQ[j],16); \
}

// layer1: fused gather + GEMM + stats
__global__ __launch_bounds__(256) void gemm_l1(const float* __restrict__ W1){
    __shared__ float sh_h[64][68];
    __shared__ float sh_w[67][68];
    __shared__ float sh_sum[64], sh_sq[64];
    int tid=threadIdx.x, blk=blockIdx.x;
    for(int e=tid;e<64*67;e+=256){ int o=e/67, c=e-o*67; sh_w[c][o]=W1[e]; }
    if(tid<64){ sh_sum[tid]=0.f; sh_sq[tid]=0.f; }
    {
        int r=tid>>2, q=tid&3;
        int grp=blk*2+(r>>5);
        int b=grp>>10;
        int i=d_idx[(size_t)grp*SS+(r&31)];
        const float4* fr=(const float4*)(d_featT+((size_t)b*NN+i)*CC);
#pragma unroll
        for(int k=0;k<4;k++){
            float4 v=fr[q*4+k];
            int o0=3+q*16+k*4;
            sh_h[r][o0+0]=v.x; sh_h[r][o0+1]=v.y; sh_h[r][o0+2]=v.z; sh_h[r][o0+3]=v.w;
        }
        if(q==0){
            const float* xt=d_xyzT+(size_t)b*3*NN;
            const float* cp=d_newxyz+(size_t)grp*3;
            sh_h[r][0]=__fsub_rn(xt[i],      cp[0]);
            sh_h[r][1]=__fsub_rn(xt[NN+i],   cp[1]);
            sh_h[r][2]=__fsub_rn(xt[2*NN+i], cp[2]);
        }
    }
    __syncthreads();
    int og=tid&7, sp=tid>>3, r0=sp*2;
    float acc0[8]={0,0,0,0,0,0,0,0}, acc1[8]={0,0,0,0,0,0,0,0};
    GEMM_BODY(67, sh_h, sh_w, acc0, acc1, r0, og)
    size_t base=((size_t)blk*64+r0)*64+og*8;
    STORE2x8(d_y1, base, acc0, acc1, 64)
    float ts[8],tq[8];
#pragma unroll
    for(int j=0;j<8;j++){ ts[j]=acc0[j]+acc1[j]; tq[j]=acc0[j]*acc0[j]+acc1[j]*acc1[j]; }
    STATS_RED_64(ts,tq)
    int lane=tid&31;
    if(lane<8)
#pragma unroll
        for(int j=0;j<8;j++){
            atomicAdd(&sh_sum[lane*8+j],ts[j]);
            atomicAdd(&sh_sq[lane*8+j],tq[j]);
        }
    __syncthreads();
    if(tid<64){ atomicAdd(&g_s1[tid],(double)sh_sum[tid]); atomicAdd(&g_q1[tid],(double)sh_sq[tid]); }
}

__global__ void mkscale_kernel(const float* __restrict__ g, const float* __restrict__ bb,
                               int layer, int Cn){
    int o=threadIdx.x;
    if(o>=Cn) return;
    const double inv=1.0/(double)NROWS;
    double s,q;
    if(layer==1){s=g_s1[o];q=g_q1[o];}
    else if(layer==2){s=g_s2[o];q=g_q2[o];}
    else {s=g_s3[o];q=g_q3[o];}
    double m=s*inv, v=q*inv-m*m;
    double aa=(double)g[o]/sqrt(v+1e-5);
    float af=(float)aa, cf=(float)((double)bb[o]-m*aa);
    if(layer==1){g_a1[o]=af;g_c1[o]=cf;}
    else if(layer==2){g_a2[o]=af;g_c2[o]=cf;}
    else {g_a3[o]=af;g_c3[o]=cf;}
}

// layer2: BN1+ReLU on load, GEMM, raw y2 out + stats
__global__ __launch_bounds__(256) void gemm_l2(const float* __restrict__ W2){
    __shared__ float sh_x[64][68];
    __shared__ float sh_w[64][68];
    __shared__ float sh_sum[64], sh_sq[64];
    int tid=threadIdx.x, blk=blockIdx.x;
    for(int e=tid;e<64*64;e+=256){ int o=e>>6, c=e&63; sh_w[c][o]=W2[e]; }
    if(tid<64){ sh_sum[tid]=0.f; sh_sq[tid]=0.f; }
    {
        int r=tid>>2, q=tid&3;
        const float4* src=(const float4*)(d_y1+((size_t)blk*64+r)*64+q*16);
#pragma unroll
        for(int k=0;k<4;k++){
            float4 v=src[k];
            int c0=q*16+k*4;
            sh_x[r][c0+0]=fmaxf(fmaf(g_a1[c0+0],v.x,g_c1[c0+0]),0.f);
            sh_x[r][c0+1]=fmaxf(fmaf(g_a1[c0+1],v.y,g_c1[c0+1]),0.f);
            sh_x[r][c0+2]=fmaxf(fmaf(g_a1[c0+2],v.z,g_c1[c0+2]),0.f);
            sh_x[r][c0+3]=fmaxf(fmaf(g_a1[c0+3],v.w,g_c1[c0+3]),0.f);
        }
    }
    __syncthreads();
    int og=tid&7, sp=tid>>3, r0=sp*2;
    float acc0[8]={0,0,0,0,0,0,0,0}, acc1[8]={0,0,0,0,0,0,0,0};
    GEMM_BODY(64, sh_x, sh_w, acc0, acc1, r0, og)
    size_t base=((size_t)blk*64+r0)*64+og*8;
    STORE2x8(d_y2, base, acc0, acc1, 64)
    float ts[8],tq[8];
#pragma unroll
    for(int j=0;j<8;j++){ ts[j]=acc0[j]+acc1[j]; tq[j]=acc0[j]*acc0[j]+acc1[j]*acc1[j]; }
    STATS_RED_64(ts,tq)
    int lane=tid&31;
    if(lane<8)
#pragma unroll
        for(int j=0;j<8;j++){
            atomicAdd(&sh_sum[lane*8+j],ts[j]);
            atomicAdd(&sh_sq[lane*8+j],tq[j]);
        }
    __syncthreads();
    if(tid<64){ atomicAdd(&g_s2[tid],(double)sh_sum[tid]); atomicAdd(&g_q2[tid],(double)sh_sq[tid]); }
}

// layer3: BN2+ReLU on load, GEMM, fused stats + per-group max (no y3 materialization)
__global__ __launch_bounds__(256) void gemm_l3(const float* __restrict__ W3){
    __shared__ float sh_x[32][68];
    __shared__ float sh_w[64][132];
    __shared__ float sh_sum[128], sh_sq[128];
    __shared__ unsigned sh_max[128];
    int tid=threadIdx.x, blk=blockIdx.x;   // blk = one group of 32 samples
    for(int e=tid;e<128*64;e+=256){ int o=e>>6, c=e&63; sh_w[c][o]=W3[e]; }
    if(tid<128){ sh_sum[tid]=0.f; sh_sq[tid]=0.f; sh_max[tid]=0u; }
    {
        int r=tid>>3, q=tid&7;
        const float4* src=(const float4*)(d_y2+((size_t)blk*32+r)*64+q*8);
#pragma unroll
        for(int k=0;k<2;k++){
            float4 v=src[k];
            int c0=q*8+k*4;
            sh_x[r][c0+0]=fmaxf(fmaf(g_a2[c0+0],v.x,g_c2[c0+0]),0.f);
            sh_x[r][c0+1]=fmaxf(fmaf(g_a2[c0+1],v.y,g_c2[c0+1]),0.f);
            sh_x[r][c0+2]=fmaxf(fmaf(g_a2[c0+2],v.z,g_c2[c0+2]),0.f);
            sh_x[r][c0+3]=fmaxf(fmaf(g_a2[c0+3],v.w,g_c2[c0+3]),0.f);
        }
    }
    __syncthreads();
    int og=tid&15, sp=tid>>4, r0=sp*2;
    float acc0[8]={0,0,0,0,0,0,0,0}, acc1[8]={0,0,0,0,0,0,0,0};
    GEMM_BODY(64, sh_x, sh_w, acc0, acc1, r0, og)
    float ts[8],tq[8],tm[8];
#pragma unroll
    for(int j=0;j<8;j++){
        ts[j]=acc0[j]+acc1[j];
        tq[j]=acc0[j]*acc0[j]+acc1[j]*acc1[j];
        tm[j]=fmaxf(acc0[j],acc1[j]);
    }
    // warp covers 2 row-pairs (lane bit 4); butterfly over bit 4
#pragma unroll
    for(int j=0;j<8;j++){
        ts[j]+=__shfl_xor_sync(0xffffffffu,ts[j],16);
        tq[j]+=__shfl_xor_sync(0xffffffffu,tq[j],16);
        tm[j]=fmaxf(tm[j],__shfl_xor_sync(0xffffffffu,tm[j],16));
    }
    int lane=tid&31;
    if(lane<16)
#pragma unroll
        for(int j=0;j<8;j++){
            int col=lane*8+j;
            atomicAdd(&sh_sum[col],ts[j]);
            atomicAdd(&sh_sq[col],tq[j]);
            atomicMax(&sh_max[col],fkey(tm[j]));
        }
    __syncthreads();
    if(tid<128){
        atomicAdd(&g_s3[tid],(double)sh_sum[tid]);
        atomicAdd(&g_q3[tid],(double)sh_sq[tid]);
        d_m3[(size_t)blk*128+tid]=finv(sh_max[tid]);
    }
}

__global__ void final_kernel(float* __restrict__ outf){
    __shared__ float t[32][33];
    int b=blockIdx.z, o0=blockIdx.y*32, p0=blockIdx.x*32;
#pragma unroll
    for(int k=0;k<32;k+=8){
        int p=p0+threadIdx.y+k, o=o0+threadIdx.x;
        float v=d_m3[((size_t)b*PP+p)*128+o];
        t[threadIdx.y+k][threadIdx.x]=fmaxf(fmaf(g_a3[o],v,g_c3[o]),0.f);
    }
    __syncthreads();
#pragma unroll
    for(int k=0;k<32;k+=8){
        int o=o0+threadIdx.y+k;
        outf[((size_t)b*128+o)*PP+p0+threadIdx.x]=t[threadIdx.x][threadIdx.y+k];
    }
}

extern "C" void kernel_launch(void* const* d_in, const int* in_sizes, int n_in,
                              void* d_out, int out_size){
    const float* xyz =(const float*)d_in[0];
    const float* feat=(const float*)d_in[1];
    const float* W1  =(const float*)d_in[2];
    const float* g1  =(const float*)d_in[3];
    const float* b1  =(const float*)d_in[4];
    const float* W2  =(const float*)d_in[5];
    const float* g2  =(const float*)d_in[6];
    const float* b2  =(const float*)d_in[7];
    const float* W3  =(const float*)d_in[8];
    const float* g3  =(const float*)d_in[9];
    const float* b3  =(const float*)d_in[10];
    float* out=(float*)d_out;
    float* out_newxyz=out;
    float* out_feat  =out+(size_t)BB*PP*3;

    zero_stats<<<1,128>>>();
    {
        dim3 g(NN/32, CC/32, BB), b(32,8);
        transpose_feat<<<g,b>>>(feat);
    }
    {
        dim3 g(NN/256, BB);
        xyz_soa<<<g,256>>>(xyz);
    }
    fps_kernel<<<BB,1024>>>(xyz, out_newxyz);
    ballq_kernel<<<(BB*PP)/4,128>>>();
    gemm_l1<<<NROWS/64,256>>>(W1);
    mkscale_kernel<<<1,128>>>(g1,b1,1,64);
    gemm_l2<<<NROWS/64,256>>>(W2);
    mkscale_kernel<<<1,128>>>(g2,b2,2,64);
    gemm_l3<<<NROWS/32,256>>>(W3);
    mkscale_kernel<<<1,128>>>(g3,b3,3,128);
    {
        dim3 g(PP/32, 128/32, BB), b(32,8);
        final_kernel<<<g,b>>>(out_feat);
    }
}

// round 7
// speedup vs baseline: 1.4431x; 1.0344x over previous
#include <cuda_runtime.h>
#include <math.h>

#define BB 16
#define NN 4096
#define CC 64
#define PP 1024
#define SS 32
#define NROWS (BB*PP*SS)   // 524288

__device__ float  d_featT[(size_t)BB*NN*CC];
__device__ float  d_xyzT[(size_t)BB*3*NN];
__device__ float  d_newxyz[BB*PP*3];
__device__ int    d_idx[BB*PP*SS];
__device__ float  d_y1[(size_t)NROWS*64];
__device__ float  d_y2[(size_t)NROWS*64];
__device__ float  d_m3[(size_t)BB*PP*128];
__device__ double g_s1[64], g_q1[64], g_s2[64], g_q2[64], g_s3[128], g_q3[128];
__device__ float  g_a1[64], g_c1[64], g_a2[64], g_c2[64], g_a3[128], g_c3[128];

__device__ __forceinline__ float sqdist(float ax,float ay,float az,float bx,float by,float bz){
    float dx=__fsub_rn(ax,bx), dy=__fsub_rn(ay,by), dz=__fsub_rn(az,bz);
    return __fadd_rn(__fadd_rn(__fmul_rn(dx,dx),__fmul_rn(dy,dy)),__fmul_rn(dz,dz));
}
__device__ __forceinline__ unsigned fkey(float f){
    unsigned u=__float_as_uint(f); return (u&0x80000000u)?~u:(u|0x80000000u);
}
__device__ __forceinline__ float finv(unsigned k){
    unsigned u=(k&0x80000000u)?(k&0x7fffffffu):~k; return __uint_as_float(u);
}

__global__ void zero_stats(){
    int t=threadIdx.x;
    if(t<64){g_s1[t]=0.0;g_q1[t]=0.0;g_s2[t]=0.0;g_q2[t]=0.0;}
    if(t<128){g_s3[t]=0.0;g_q3[t]=0.0;}
}

__global__ void transpose_feat(const float* __restrict__ f){
    __shared__ float t[32][33];
    int b=blockIdx.z, c0=blockIdx.y*32, n0=blockIdx.x*32;
    const float* src=f+((size_t)b*CC+c0)*NN+n0;
#pragma unroll
    for(int k=0;k<32;k+=8)
        t[threadIdx.y+k][threadIdx.x]=src[(size_t)(threadIdx.y+k)*NN+threadIdx.x];
    __syncthreads();
    float* dst=d_featT+((size_t)b*NN+n0)*CC+c0;
#pragma unroll
    for(int k=0;k<32;k+=8)
        dst[(size_t)(threadIdx.y+k)*CC+threadIdx.x]=t[threadIdx.x][threadIdx.y+k];
}

__global__ __launch_bounds__(256) void xyz_soa(const float* __restrict__ xyz){
    __shared__ float s[768];
    int b=blockIdx.y, n0=blockIdx.x*256;
    const float* src=xyz+((size_t)b*NN+n0)*3;
    for(int k=threadIdx.x;k<768;k+=256) s[k]=src[k];
    __syncthreads();
    float* dst=d_xyzT+(size_t)b*3*NN;
    int n=n0+threadIdx.x;
    dst[n]      =s[threadIdx.x*3+0];
    dst[NN+n]   =s[threadIdx.x*3+1];
    dst[2*NN+n] =s[threadIdx.x*3+2];
}

// FPS: one bar/iter, redundant block reduce, coords via broadcast LDG
__global__ __launch_bounds__(1024,1) void fps_kernel(const float* __restrict__ xyz,
                                                     float* __restrict__ out_newxyz){
    int b=blockIdx.x, tid=threadIdx.x;
    int warp=tid>>5, lane=tid&31;
    const float* X=xyz+(size_t)b*NN*3;
    float px[4],py[4],pz[4],dd[4];
#pragma unroll
    for(int j=0;j<4;j++){
        int p=tid+j*1024;
        px[j]=X[p*3+0]; py[j]=X[p*3+1]; pz[j]=X[p*3+2]; dd[j]=1e10f;
    }
    __shared__ unsigned long long s_red[2][32];
    float lx=__ldg(&X[0]), ly=__ldg(&X[1]), lz=__ldg(&X[2]);
    if(tid==0){
        float* o1=d_newxyz+(size_t)b*PP*3; o1[0]=lx;o1[1]=ly;o1[2]=lz;
        float* o2=out_newxyz+(size_t)b*PP*3; o2[0]=lx;o2[1]=ly;o2[2]=lz;
    }
    for(int it=1; it<PP; it++){
        int p=it&1;
        unsigned long long best=0ull;
#pragma unroll
        for(int j=0;j<4;j++){
            float d=sqdist(px[j],py[j],pz[j],lx,ly,lz);
            float nd=fminf(dd[j],d); dd[j]=nd;
            unsigned long long k=((unsigned long long)__float_as_uint(nd)<<32)
                               |(unsigned)(NN-1-(tid+j*1024));
            best=(k>best)?k:best;
        }
#pragma unroll
        for(int off=16;off>0;off>>=1){
            unsigned long long o=__shfl_xor_sync(0xffffffffu,best,off);
            best=(o>best)?o:best;
        }
        if(lane==0) s_red[p][warp]=best;
        __syncthreads();
        unsigned long long v=s_red[p][lane];
#pragma unroll
        for(int off=16;off>0;off>>=1){
            unsigned long long o=__shfl_xor_sync(0xffffffffu,v,off);
            v=(o>v)?o:v;
        }
        int widx=(NN-1)-(int)(unsigned)(v&0xffffffffu);
        lx=__ldg(&X[widx*3+0]);
        ly=__ldg(&X[widx*3+1]);
        lz=__ldg(&X[widx*3+2]);
        if(tid==0){
            float* o1=d_newxyz+((size_t)b*PP+it)*3; o1[0]=lx;o1[1]=ly;o1[2]=lz;
            float* o2=out_newxyz+((size_t)b*PP+it)*3; o2[0]=lx;o2[1]=ly;o2[2]=lz;
        }
    }
}

__global__ __launch_bounds__(128) void ballq_kernel(){
    int warp=blockIdx.x*4+(threadIdx.x>>5);
    int lane=threadIdx.x&31;
    int b=warp>>10;
    const float* Xx=d_xyzT+(size_t)b*3*NN;
    const float* Xy=Xx+NN;
    const float* Xz=Xx+2*NN;
    float cx=d_newxyz[warp*3+0], cy=d_newxyz[warp*3+1], cz=d_newxyz[warp*3+2];
    int* out=d_idx+(size_t)warp*SS;
    const float R2=0.04f;
    int cnt=0, firstIdx=-1;
    for(int base=0; base<NN && cnt<SS; base+=32){
        int n=base+lane;
        bool in=sqdist(cx,cy,cz,Xx[n],Xy[n],Xz[n])<R2;
        unsigned m=__ballot_sync(0xffffffffu,in);
        if(firstIdx<0 && m) firstIdx=base+__ffs(m)-1;
        if(in){
            int pos=cnt+__popc(m&((1u<<lane)-1u));
            if(pos<SS) out[pos]=n;
        }
        cnt+=__popc(m);
    }
    int written=cnt<SS?cnt:SS;
    if(lane>=written) out[lane]=firstIdx;
}

#define GEMM_BODY(Kc, SHX, SHW, ACC0, ACC1, R0, OG) \
_Pragma("unroll 4") \
for(int c=0;c<(Kc);c++){ \
    float h0=SHX[R0][c], h1=SHX[R0+1][c]; \
    const float4* wp=(const float4*)&SHW[c][(OG)*8]; \
    float4 wa=wp[0], wb=wp[1]; \
    ACC0[0]=fmaf(h0,wa.x,ACC0[0]); ACC1[0]=fmaf(h1,wa.x,ACC1[0]); \
    ACC0[1]=fmaf(h0,wa.y,ACC0[1]); ACC1[1]=fmaf(h1,wa.y,ACC1[1]); \
    ACC0[2]=fmaf(h0,wa.z,ACC0[2]); ACC1[2]=fmaf(h1,wa.z,ACC1[2]); \
    ACC0[3]=fmaf(h0,wa.w,ACC0[3]); ACC1[3]=fmaf(h1,wa.w,ACC1[3]); \
    ACC0[4]=fmaf(h0,wb.x,ACC0[4]); ACC1[4]=fmaf(h1,wb.x,ACC1[4]); \
    ACC0[5]=fmaf(h0,wb.y,ACC0[5]); ACC1[5]=fmaf(h1,wb.y,ACC1[5]); \
    ACC0[6]=fmaf(h0,wb.z,ACC0[6]); ACC1[6]=fmaf(h1,wb.z,ACC1[6]); \
    ACC0[7]=fmaf(h0,wb.w,ACC0[7]); ACC1[7]=fmaf(h1,wb.w,ACC1[7]); \
}

#define STORE2x8(DST, BASE, A0, A1, RS) \
    ((float4*)((DST)+(BASE)))[0]=make_float4(A0[0],A0[1],A0[2],A0[3]); \
    ((float4*)((DST)+(BASE)))[1]=make_float4(A0[4],A0[5],A0[6],A0[7]); \
    ((float4*)((DST)+(BASE)+(RS)))[0]=make_float4(A1[0],A1[1],A1[2],A1[3]); \
    ((float4*)((DST)+(BASE)+(RS)))[1]=make_float4(A1[4],A1[5],A1[6],A1[7]);

#define STATS_RED_64(TS,TQ) \
_Pragma("unroll") \
for(int j=0;j<8;j++){ \
    TS[j]+=__shfl_xor_sync(0xffffffffu,TS[j],8); \
    TQ[j]+=__shfl_xor_sync(0xffffffffu,TQ[j],8); \
    TS[j]+=__shfl_xor_sync(0xffffffffu,TS[j],16); \
    TQ[j]+=__shfl_xor_sync(0xffffffffu,TQ[j],16); \
}

__global__ __launch_bounds__(256) void gemm_l1(const float* __restrict__ W1){
    __shared__ float sh_h[64][68];
    __shared__ float sh_w[67][68];
    __shared__ float sh_sum[64], sh_sq[64];
    int tid=threadIdx.x, blk=blockIdx.x;
    for(int e=tid;e<64*67;e+=256){ int o=e/67, c=e-o*67; sh_w[c][o]=W1[e]; }
    if(tid<64){ sh_sum[tid]=0.f; sh_sq[tid]=0.f; }
    {
        int r=tid>>2, q=tid&3;
        int grp=blk*2+(r>>5);
        int b=grp>>10;
        int i=d_idx[(size_t)grp*SS+(r&31)];
        const float4* fr=(const float4*)(d_featT+((size_t)b*NN+i)*CC);
#pragma unroll
        for(int k=0;k<4;k++){
            float4 v=fr[q*4+k];
            int o0=3+q*16+k*4;
            sh_h[r][o0+0]=v.x; sh_h[r][o0+1]=v.y; sh_h[r][o0+2]=v.z; sh_h[r][o0+3]=v.w;
        }
        if(q==0){
            const float* xt=d_xyzT+(size_t)b*3*NN;
            const float* cp=d_newxyz+(size_t)grp*3;
            sh_h[r][0]=__fsub_rn(xt[i],      cp[0]);
            sh_h[r][1]=__fsub_rn(xt[NN+i],   cp[1]);
            sh_h[r][2]=__fsub_rn(xt[2*NN+i], cp[2]);
        }
    }
    __syncthreads();
    int og=tid&7, sp=tid>>3, r0=sp*2;
    float acc0[8]={0,0,0,0,0,0,0,0}, acc1[8]={0,0,0,0,0,0,0,0};
    GEMM_BODY(67, sh_h, sh_w, acc0, acc1, r0, og)
    size_t base=((size_t)blk*64+r0)*64+og*8;
    STORE2x8(d_y1, base, acc0, acc1, 64)
    float ts[8],tq[8];
#pragma unroll
    for(int j=0;j<8;j++){ ts[j]=acc0[j]+acc1[j]; tq[j]=acc0[j]*acc0[j]+acc1[j]*acc1[j]; }
    STATS_RED_64(ts,tq)
    int lane=tid&31;
    if(lane<8)
#pragma unroll
        for(int j=0;j<8;j++){
            atomicAdd(&sh_sum[lane*8+j],ts[j]);
            atomicAdd(&sh_sq[lane*8+j],tq[j]);
        }
    __syncthreads();
    if(tid<64){ atomicAdd(&g_s1[tid],(double)sh_sum[tid]); atomicAdd(&g_q1[tid],(double)sh_sq[tid]); }
}

__global__ void mkscale_kernel(const float* __restrict__ g, const float* __restrict__ bb,
                               int layer, int Cn){
    int o=threadIdx.x;
    if(o>=Cn) return;
    const double inv=1.0/(double)NROWS;
    double s,q;
    if(layer==1){s=g_s1[o];q=g_q1[o];}
    else if(layer==2){s=g_s2[o];q=g_q2[o];}
    else {s=g_s3[o];q=g_q3[o];}
    double m=s*inv, v=q*inv-m*m;
    double aa=(double)g[o]/sqrt(v+1e-5);
    float af=(float)aa, cf=(float)((double)bb[o]-m*aa);
    if(layer==1){g_a1[o]=af;g_c1[o]=cf;}
    else if(layer==2){g_a2[o]=af;g_c2[o]=cf;}
    else {g_a3[o]=af;g_c3[o]=cf;}
}

__global__ __launch_bounds__(256) void gemm_l2(const float* __restrict__ W2){
    __shared__ float sh_x[64][68];
    __shared__ float sh_w[64][68];
    __shared__ float sh_sum[64], sh_sq[64];
    int tid=threadIdx.x, blk=blockIdx.x;
    for(int e=tid;e<64*64;e+=256){ int o=e>>6, c=e&63; sh_w[c][o]=W2[e]; }
    if(tid<64){ sh_sum[tid]=0.f; sh_sq[tid]=0.f; }
    {
        int r=tid>>2, q=tid&3;
        const float4* src=(const float4*)(d_y1+((size_t)blk*64+r)*64+q*16);
#pragma unroll
        for(int k=0;k<4;k++){
            float4 v=src[k];
            int c0=q*16+k*4;
            sh_x[r][c0+0]=fmaxf(fmaf(g_a1[c0+0],v.x,g_c1[c0+0]),0.f);
            sh_x[r][c0+1]=fmaxf(fmaf(g_a1[c0+1],v.y,g_c1[c0+1]),0.f);
            sh_x[r][c0+2]=fmaxf(fmaf(g_a1[c0+2],v.z,g_c1[c0+2]),0.f);
            sh_x[r][c0+3]=fmaxf(fmaf(g_a1[c0+3],v.w,g_c1[c0+3]),0.f);
        }
    }
    __syncthreads();
    int og=tid&7, sp=tid>>3, r0=sp*2;
    float acc0[8]={0,0,0,0,0,0,0,0}, acc1[8]={0,0,0,0,0,0,0,0};
    GEMM_BODY(64, sh_x, sh_w, acc0, acc1, r0, og)
    size_t base=((size_t)blk*64+r0)*64+og*8;
    STORE2x8(d_y2, base, acc0, acc1, 64)
    float ts[8],tq[8];
#pragma unroll
    for(int j=0;j<8;j++){ ts[j]=acc0[j]+acc1[j]; tq[j]=acc0[j]*acc0[j]+acc1[j]*acc1[j]; }
    STATS_RED_64(ts,tq)
    int lane=tid&31;
    if(lane<8)
#pragma unroll
        for(int j=0;j<8;j++){
            atomicAdd(&sh_sum[lane*8+j],ts[j]);
            atomicAdd(&sh_sq[lane*8+j],tq[j]);
        }
    __syncthreads();
    if(tid<64){ atomicAdd(&g_s2[tid],(double)sh_sum[tid]); atomicAdd(&g_q2[tid],(double)sh_sq[tid]); }
}

__global__ __launch_bounds__(256) void gemm_l3(const float* __restrict__ W3){
    __shared__ float sh_x[32][68];
    __shared__ float sh_w[64][132];
    __shared__ float sh_sum[128], sh_sq[128];
    __shared__ unsigned sh_max[128];
    int tid=threadIdx.x, blk=blockIdx.x;
    for(int e=tid;e<128*64;e+=256){ int o=e>>6, c=e&63; sh_w[c][o]=W3[e]; }
    if(tid<128){ sh_sum[tid]=0.f; sh_sq[tid]=0.f; sh_max[tid]=0u; }
    {
        int r=tid>>3, q=tid&7;
        const float4* src=(const float4*)(d_y2+((size_t)blk*32+r)*64+q*8);
#pragma unroll
        for(int k=0;k<2;k++){
            float4 v=src[k];
            int c0=q*8+k*4;
            sh_x[r][c0+0]=fmaxf(fmaf(g_a2[c0+0],v.x,g_c2[c0+0]),0.f);
            sh_x[r][c0+1]=fmaxf(fmaf(g_a2[c0+1],v.y,g_c2[c0+1]),0.f);
            sh_x[r][c0+2]=fmaxf(fmaf(g_a2[c0+2],v.z,g_c2[c0+2]),0.f);
            sh_x[r][c0+3]=fmaxf(fmaf(g_a2[c0+3],v.w,g_c2[c0+3]),0.f);
        }
    }
    __syncthreads();
    int og=tid&15, sp=tid>>4, r0=sp*2;
    float acc0[8]={0,0,0,0,0,0,0,0}, acc1[8]={0,0,0,0,0,0,0,0};
    GEMM_BODY(64, sh_x, sh_w, acc0, acc1, r0, og)
    float ts[8],tq[8],tm[8];
#pragma unroll
    for(int j=0;j<8;j++){
        ts[j]=acc0[j]+acc1[j];
        tq[j]=acc0[j]*acc0[j]+acc1[j]*acc1[j];
        tm[j]=fmaxf(acc0[j],acc1[j]);
    }
#pragma unroll
    for(int j=0;j<8;j++){
        ts[j]+=__shfl_xor_sync(0xffffffffu,ts[j],16);
        tq[j]+=__shfl_xor_sync(0xffffffffu,tq[j],16);
        tm[j]=fmaxf(tm[j],__shfl_xor_sync(0xffffffffu,tm[j],16));
    }
    int lane=tid&31;
    if(lane<16)
#pragma unroll
        for(int j=0;j<8;j++){
            int col=lane*8+j;
            atomicAdd(&sh_sum[col],ts[j]);
            atomicAdd(&sh_sq[col],tq[j]);
            atomicMax(&sh_max[col],fkey(tm[j]));
        }
    __syncthreads();
    if(tid<128){
        atomicAdd(&g_s3[tid],(double)sh_sum[tid]);
        atomicAdd(&g_q3[tid],(double)sh_sq[tid]);
        d_m3[(size_t)blk*128+tid]=finv(sh_max[tid]);
    }
}

__global__ void final_kernel(float* __restrict__ outf){
    __shared__ float t[32][33];
    int b=blockIdx.z, o0=blockIdx.y*32, p0=blockIdx.x*32;
#pragma unroll
    for(int k=0;k<32;k+=8){
        int p=p0+threadIdx.y+k, o=o0+threadIdx.x;
        float v=d_m3[((size_t)b*PP+p)*128+o];
        t[threadIdx.y+k][threadIdx.x]=fmaxf(fmaf(g_a3[o],v,g_c3[o]),0.f);
    }
    __syncthreads();
#pragma unroll
    for(int k=0;k<32;k+=8){
        int o=o0+threadIdx.y+k;
        outf[((size_t)b*128+o)*PP+p0+threadIdx.x]=t[threadIdx.x][threadIdx.y+k];
    }
}

extern "C" void kernel_launch(void* const* d_in, const int* in_sizes, int n_in,
                              void* d_out, int out_size){
    const float* xyz =(const float*)d_in[0];
    const float* feat=(const float*)d_in[1];
    const float* W1  =(const float*)d_in[2];
    const float* g1  =(const float*)d_in[3];
    const float* b1  =(const float*)d_in[4];
    const float* W2  =(const float*)d_in[5];
    const float* g2  =(const float*)d_in[6];
    const float* b2  =(const float*)d_in[7];
    const float* W3  =(const float*)d_in[8];
    const float* g3  =(const float*)d_in[9];
    const float* b3  =(const float*)d_in[10];
    float* out=(float*)d_out;
    float* out_newxyz=out;
    float* out_feat  =out+(size_t)BB*PP*3;

    zero_stats<<<1,128>>>();
    {
        dim3 g(NN/32, CC/32, BB), b(32,8);
        transpose_feat<<<g,b>>>(feat);
    }
    {
        dim3 g(NN/256, BB);
        xyz_soa<<<g,256>>>(xyz);
    }
    fps_kernel<<<BB,1024>>>(xyz, out_newxyz);
    ballq_kernel<<<(BB*PP)/4,128>>>();
    gemm_l1<<<NROWS/64,256>>>(W1);
    mkscale_kernel<<<1,128>>>(g1,b1,1,64);
    gemm_l2<<<NROWS/64,256>>>(W2);
    mkscale_kernel<<<1,128>>>(g2,b2,2,64);
    gemm_l3<<<NROWS/32,256>>>(W3);
    mkscale_kernel<<<1,128>>>(g3,b3,3,128);
    {
        dim3 g(PP/32, 128/32, BB), b(32,8);
        final_kernel<<<g,b>>>(out_feat);
    }
}

// round 8
// speedup vs baseline: 1.5385x; 1.0661x over previous
#include <cuda_runtime.h>
#include <math.h>

#define BB 16
#define NN 4096
#define CC 64
#define PP 1024
#define SS 32
#define NROWS (BB*PP*SS)   // 524288

__device__ float  d_featT[(size_t)BB*NN*CC];
__device__ float  d_xyzT[(size_t)BB*3*NN];
__device__ float  d_newxyz[BB*PP*3];
__device__ int    d_idx[BB*PP*SS];
__device__ float  d_y1[(size_t)NROWS*64];
__device__ float  d_y2[(size_t)NROWS*64];
__device__ float  d_m3[(size_t)BB*PP*128];
__device__ double g_s1[64], g_q1[64], g_s2[64], g_q2[64], g_s3[128], g_q3[128];
__device__ float  g_a1[64], g_c1[64], g_a2[64], g_c2[64], g_a3[128], g_c3[128];

__device__ __forceinline__ float sqdist(float ax,float ay,float az,float bx,float by,float bz){
    float dx=__fsub_rn(ax,bx), dy=__fsub_rn(ay,by), dz=__fsub_rn(az,bz);
    return __fadd_rn(__fadd_rn(__fmul_rn(dx,dx),__fmul_rn(dy,dy)),__fmul_rn(dz,dz));
}
__device__ __forceinline__ unsigned fkey(float f){
    unsigned u=__float_as_uint(f); return (u&0x80000000u)?~u:(u|0x80000000u);
}
__device__ __forceinline__ float finv(unsigned k){
    unsigned u=(k&0x80000000u)?(k&0x7fffffffu):~k; return __uint_as_float(u);
}

__global__ void zero_stats(){
    int t=threadIdx.x;
    if(t<64){g_s1[t]=0.0;g_q1[t]=0.0;g_s2[t]=0.0;g_q2[t]=0.0;}
    if(t<128){g_s3[t]=0.0;g_q3[t]=0.0;}
}

__global__ void transpose_feat(const float* __restrict__ f){
    __shared__ float t[32][33];
    int b=blockIdx.z, c0=blockIdx.y*32, n0=blockIdx.x*32;
    const float* src=f+((size_t)b*CC+c0)*NN+n0;
#pragma unroll
    for(int k=0;k<32;k+=8)
        t[threadIdx.y+k][threadIdx.x]=src[(size_t)(threadIdx.y+k)*NN+threadIdx.x];
    __syncthreads();
    float* dst=d_featT+((size_t)b*NN+n0)*CC+c0;
#pragma unroll
    for(int k=0;k<32;k+=8)
        dst[(size_t)(threadIdx.y+k)*CC+threadIdx.x]=t[threadIdx.x][threadIdx.y+k];
}

__global__ __launch_bounds__(256) void xyz_soa(const float* __restrict__ xyz){
    __shared__ float s[768];
    int b=blockIdx.y, n0=blockIdx.x*256;
    const float* src=xyz+((size_t)b*NN+n0)*3;
    for(int k=threadIdx.x;k<768;k+=256) s[k]=src[k];
    __syncthreads();
    float* dst=d_xyzT+(size_t)b*3*NN;
    int n=n0+threadIdx.x;
    dst[n]      =s[threadIdx.x*3+0];
    dst[NN+n]   =s[threadIdx.x*3+1];
    dst[2*NN+n] =s[threadIdx.x*3+2];
}

// FPS: REDUX-based argmax (value max, then min index among bit-equal maxima)
__global__ __launch_bounds__(1024,1) void fps_kernel(const float* __restrict__ xyz,
                                                     float* __restrict__ out_newxyz){
    int b=blockIdx.x, tid=threadIdx.x;
    int warp=tid>>5, lane=tid&31;
    const float* X=xyz+(size_t)b*NN*3;
    float px[4],py[4],pz[4],dd[4];
#pragma unroll
    for(int j=0;j<4;j++){
        int p=tid+j*1024;
        px[j]=X[p*3+0]; py[j]=X[p*3+1]; pz[j]=X[p*3+2]; dd[j]=1e10f;
    }
    __shared__ unsigned s_d[2][32];
    __shared__ unsigned s_i[2][32];
    float lx=__ldg(&X[0]), ly=__ldg(&X[1]), lz=__ldg(&X[2]);
    if(tid==0){
        float* o1=d_newxyz+(size_t)b*PP*3; o1[0]=lx;o1[1]=ly;o1[2]=lz;
        float* o2=out_newxyz+(size_t)b*PP*3; o2[0]=lx;o2[1]=ly;o2[2]=lz;
    }
    for(int it=1; it<PP; it++){
        int p=it&1;
#pragma unroll
        for(int j=0;j<4;j++){
            float d=sqdist(px[j],py[j],pz[j],lx,ly,lz);
            dd[j]=fminf(dd[j],d);
        }
        // thread-local max with lowest global index (index = tid + j*1024)
        float m=fmaxf(fmaf(0.f,0.f,fmaxf(dd[0],dd[1])),fmaxf(dd[2],dd[3]));
        unsigned cand=0xFFFFFFFFu;
        if(dd[3]==m) cand=tid+3072u;
        if(dd[2]==m) cand=tid+2048u;
        if(dd[1]==m) cand=tid+1024u;
        if(dd[0]==m) cand=(unsigned)tid;
        // warp reduce: dist bits are monotone (d>=0)
        unsigned mb=__float_as_uint(m);
        unsigned wmax=__reduce_max_sync(0xffffffffu, mb);
        unsigned wi=__reduce_min_sync(0xffffffffu, (mb==wmax)?cand:0xFFFFFFFFu);
        if(lane==0){ s_d[p][warp]=wmax; s_i[p][warp]=wi; }
        __syncthreads();
        // redundant block reduce in every warp (all arrive at same result)
        unsigned dv=s_d[p][lane];
        unsigned bmax=__reduce_max_sync(0xffffffffu, dv);
        unsigned widx=__reduce_min_sync(0xffffffffu, (dv==bmax)?s_i[p][lane]:0xFFFFFFFFu);
        lx=__ldg(&X[widx*3+0]);
        ly=__ldg(&X[widx*3+1]);
        lz=__ldg(&X[widx*3+2]);
        if(tid==0){
            float* o1=d_newxyz+((size_t)b*PP+it)*3; o1[0]=lx;o1[1]=ly;o1[2]=lz;
            float* o2=out_newxyz+((size_t)b*PP+it)*3; o2[0]=lx;o2[1]=ly;o2[2]=lz;
        }
    }
}

__global__ __launch_bounds__(128) void ballq_kernel(){
    int warp=blockIdx.x*4+(threadIdx.x>>5);
    int lane=threadIdx.x&31;
    int b=warp>>10;
    const float* Xx=d_xyzT+(size_t)b*3*NN;
    const float* Xy=Xx+NN;
    const float* Xz=Xx+2*NN;
    float cx=d_newxyz[warp*3+0], cy=d_newxyz[warp*3+1], cz=d_newxyz[warp*3+2];
    int* out=d_idx+(size_t)warp*SS;
    const float R2=0.04f;
    int cnt=0, firstIdx=-1;
    for(int base=0; base<NN && cnt<SS; base+=32){
        int n=base+lane;
        bool in=sqdist(cx,cy,cz,Xx[n],Xy[n],Xz[n])<R2;
        unsigned m=__ballot_sync(0xffffffffu,in);
        if(firstIdx<0 && m) firstIdx=base+__ffs(m)-1;
        if(in){
            int pos=cnt+__popc(m&((1u<<lane)-1u));
            if(pos<SS) out[pos]=n;
        }
        cnt+=__popc(m);
    }
    int written=cnt<SS?cnt:SS;
    if(lane>=written) out[lane]=firstIdx;
}

#define GEMM_BODY(Kc, SHX, SHW, ACC0, ACC1, R0, OG) \
_Pragma("unroll 4") \
for(int c=0;c<(Kc);c++){ \
    float h0=SHX[R0][c], h1=SHX[R0+1][c]; \
    const float4* wp=(const float4*)&SHW[c][(OG)*8]; \
    float4 wa=wp[0], wb=wp[1]; \
    ACC0[0]=fmaf(h0,wa.x,ACC0[0]); ACC1[0]=fmaf(h1,wa.x,ACC1[0]); \
    ACC0[1]=fmaf(h0,wa.y,ACC0[1]); ACC1[1]=fmaf(h1,wa.y,ACC1[1]); \
    ACC0[2]=fmaf(h0,wa.z,ACC0[2]); ACC1[2]=fmaf(h1,wa.z,ACC1[2]); \
    ACC0[3]=fmaf(h0,wa.w,ACC0[3]); ACC1[3]=fmaf(h1,wa.w,ACC1[3]); \
    ACC0[4]=fmaf(h0,wb.x,ACC0[4]); ACC1[4]=fmaf(h1,wb.x,ACC1[4]); \
    ACC0[5]=fmaf(h0,wb.y,ACC0[5]); ACC1[5]=fmaf(h1,wb.y,ACC1[5]); \
    ACC0[6]=fmaf(h0,wb.z,ACC0[6]); ACC1[6]=fmaf(h1,wb.z,ACC1[6]); \
    ACC0[7]=fmaf(h0,wb.w,ACC0[7]); ACC1[7]=fmaf(h1,wb.w,ACC1[7]); \
}

#define STORE2x8(DST, BASE, A0, A1, RS) \
    ((float4*)((DST)+(BASE)))[0]=make_float4(A0[0],A0[1],A0[2],A0[3]); \
    ((float4*)((DST)+(BASE)))[1]=make_float4(A0[4],A0[5],A0[6],A0[7]); \
    ((float4*)((DST)+(BASE)+(RS)))[0]=make_float4(A1[0],A1[1],A1[2],A1[3]); \
    ((float4*)((DST)+(BASE)+(RS)))[1]=make_float4(A1[4],A1[5],A1[6],A1[7]);

#define STATS_RED_64(TS,TQ) \
_Pragma("unroll") \
for(int j=0;j<8;j++){ \
    TS[j]+=__shfl_xor_sync(0xffffffffu,TS[j],8); \
    TQ[j]+=__shfl_xor_sync(0xffffffffu,TQ[j],8); \
    TS[j]+=__shfl_xor_sync(0xffffffffu,TS[j],16); \
    TQ[j]+=__shfl_xor_sync(0xffffffffu,TQ[j],16); \
}

__global__ __launch_bounds__(256) void gemm_l1(const float* __restrict__ W1){
    __shared__ float sh_h[64][68];
    __shared__ float sh_w[67][68];
    __shared__ float sh_sum[64], sh_sq[64];
    int tid=threadIdx.x, blk=blockIdx.x;
    for(int e=tid;e<64*67;e+=256){ int o=e/67, c=e-o*67; sh_w[c][o]=W1[e]; }
    if(tid<64){ sh_sum[tid]=0.f; sh_sq[tid]=0.f; }
    {
        int r=tid>>2, q=tid&3;
        int grp=blk*2+(r>>5);
        int b=grp>>10;
        int i=d_idx[(size_t)grp*SS+(r&31)];
        const float4* fr=(const float4*)(d_featT+((size_t)b*NN+i)*CC);
#pragma unroll
        for(int k=0;k<4;k++){
            float4 v=fr[q*4+k];
            int o0=3+q*16+k*4;
            sh_h[r][o0+0]=v.x; sh_h[r][o0+1]=v.y; sh_h[r][o0+2]=v.z; sh_h[r][o0+3]=v.w;
        }
        if(q==0){
            const float* xt=d_xyzT+(size_t)b*3*NN;
            const float* cp=d_newxyz+(size_t)grp*3;
            sh_h[r][0]=__fsub_rn(xt[i],      cp[0]);
            sh_h[r][1]=__fsub_rn(xt[NN+i],   cp[1]);
            sh_h[r][2]=__fsub_rn(xt[2*NN+i], cp[2]);
        }
    }
    __syncthreads();
    int og=tid&7, sp=tid>>3, r0=sp*2;
    float acc0[8]={0,0,0,0,0,0,0,0}, acc1[8]={0,0,0,0,0,0,0,0};
    GEMM_BODY(67, sh_h, sh_w, acc0, acc1, r0, og)
    size_t base=((size_t)blk*64+r0)*64+og*8;
    STORE2x8(d_y1, base, acc0, acc1, 64)
    float ts[8],tq[8];
#pragma unroll
    for(int j=0;j<8;j++){ ts[j]=acc0[j]+acc1[j]; tq[j]=acc0[j]*acc0[j]+acc1[j]*acc1[j]; }
    STATS_RED_64(ts,tq)
    int lane=tid&31;
    if(lane<8)
#pragma unroll
        for(int j=0;j<8;j++){
            atomicAdd(&sh_sum[lane*8+j],ts[j]);
            atomicAdd(&sh_sq[lane*8+j],tq[j]);
        }
    __syncthreads();
    if(tid<64){ atomicAdd(&g_s1[tid],(double)sh_sum[tid]); atomicAdd(&g_q1[tid],(double)sh_sq[tid]); }
}

__global__ void mkscale_kernel(const float* __restrict__ g, const float* __restrict__ bb,
                               int layer, int Cn){
    int o=threadIdx.x;
    if(o>=Cn) return;
    const double inv=1.0/(double)NROWS;
    double s,q;
    if(layer==1){s=g_s1[o];q=g_q1[o];}
    else if(layer==2){s=g_s2[o];q=g_q2[o];}
    else {s=g_s3[o];q=g_q3[o];}
    double m=s*inv, v=q*inv-m*m;
    double aa=(double)g[o]/sqrt(v+1e-5);
    float af=(float)aa, cf=(float)((double)bb[o]-m*aa);
    if(layer==1){g_a1[o]=af;g_c1[o]=cf;}
    else if(layer==2){g_a2[o]=af;g_c2[o]=cf;}
    else {g_a3[o]=af;g_c3[o]=cf;}
}

__global__ __launch_bounds__(256) void gemm_l2(const float* __restrict__ W2){
    __shared__ float sh_x[64][68];
    __shared__ float sh_w[64][68];
    __shared__ float sh_sum[64], sh_sq[64];
    int tid=threadIdx.x, blk=blockIdx.x;
    for(int e=tid;e<64*64;e+=256){ int o=e>>6, c=e&63; sh_w[c][o]=W2[e]; }
    if(tid<64){ sh_sum[tid]=0.f; sh_sq[tid]=0.f; }
    {
        int r=tid>>2, q=tid&3;
        const float4* src=(const float4*)(d_y1+((size_t)blk*64+r)*64+q*16);
#pragma unroll
        for(int k=0;k<4;k++){
            float4 v=src[k];
            int c0=q*16+k*4;
            sh_x[r][c0+0]=fmaxf(fmaf(g_a1[c0+0],v.x,g_c1[c0+0]),0.f);
            sh_x[r][c0+1]=fmaxf(fmaf(g_a1[c0+1],v.y,g_c1[c0+1]),0.f);
            sh_x[r][c0+2]=fmaxf(fmaf(g_a1[c0+2],v.z,g_c1[c0+2]),0.f);
            sh_x[r][c0+3]=fmaxf(fmaf(g_a1[c0+3],v.w,g_c1[c0+3]),0.f);
        }
    }
    __syncthreads();
    int og=tid&7, sp=tid>>3, r0=sp*2;
    float acc0[8]={0,0,0,0,0,0,0,0}, acc1[8]={0,0,0,0,0,0,0,0};
    GEMM_BODY(64, sh_x, sh_w, acc0, acc1, r0, og)
    size_t base=((size_t)blk*64+r0)*64+og*8;
    STORE2x8(d_y2, base, acc0, acc1, 64)
    float ts[8],tq[8];
#pragma unroll
    for(int j=0;j<8;j++){ ts[j]=acc0[j]+acc1[j]; tq[j]=acc0[j]*acc0[j]+acc1[j]*acc1[j]; }
    STATS_RED_64(ts,tq)
    int lane=tid&31;
    if(lane<8)
#pragma unroll
        for(int j=0;j<8;j++){
            atomicAdd(&sh_sum[lane*8+j],ts[j]);
            atomicAdd(&sh_sq[lane*8+j],tq[j]);
        }
    __syncthreads();
    if(tid<64){ atomicAdd(&g_s2[tid],(double)sh_sum[tid]); atomicAdd(&g_q2[tid],(double)sh_sq[tid]); }
}

__global__ __launch_bounds__(256) void gemm_l3(const float* __restrict__ W3){
    __shared__ float sh_x[32][68];
    __shared__ float sh_w[64][132];
    __shared__ float sh_sum[128], sh_sq[128];
    __shared__ unsigned sh_max[128];
    int tid=threadIdx.x, blk=blockIdx.x;
    for(int e=tid;e<128*64;e+=256){ int o=e>>6, c=e&63; sh_w[c][o]=W3[e]; }
    if(tid<128){ sh_sum[tid]=0.f; sh_sq[tid]=0.f; sh_max[tid]=0u; }
    {
        int r=tid>>3, q=tid&7;
        const float4* src=(const float4*)(d_y2+((size_t)blk*32+r)*64+q*8);
#pragma unroll
        for(int k=0;k<2;k++){
            float4 v=src[k];
            int c0=q*8+k*4;
            sh_x[r][c0+0]=fmaxf(fmaf(g_a2[c0+0],v.x,g_c2[c0+0]),0.f);
            sh_x[r][c0+1]=fmaxf(fmaf(g_a2[c0+1],v.y,g_c2[c0+1]),0.f);
            sh_x[r][c0+2]=fmaxf(fmaf(g_a2[c0+2],v.z,g_c2[c0+2]),0.f);
            sh_x[r][c0+3]=fmaxf(fmaf(g_a2[c0+3],v.w,g_c2[c0+3]),0.f);
        }
    }
    __syncthreads();
    int og=tid&15, sp=tid>>4, r0=sp*2;
    float acc0[8]={0,0,0,0,0,0,0,0}, acc1[8]={0,0,0,0,0,0,0,0};
    GEMM_BODY(64, sh_x, sh_w, acc0, acc1, r0, og)
    float ts[8],tq[8],tm[8];
#pragma unroll
    for(int j=0;j<8;j++){
        ts[j]=acc0[j]+acc1[j];
        tq[j]=acc0[j]*acc0[j]+acc1[j]*acc1[j];
        tm[j]=fmaxf(acc0[j],acc1[j]);
    }
#pragma unroll
    for(int j=0;j<8;j++){
        ts[j]+=__shfl_xor_sync(0xffffffffu,ts[j],16);
        tq[j]+=__shfl_xor_sync(0xffffffffu,tq[j],16);
        tm[j]=fmaxf(tm[j],__shfl_xor_sync(0xffffffffu,tm[j],16));
    }
    int lane=tid&31;
    if(lane<16)
#pragma unroll
        for(int j=0;j<8;j++){
            int col=lane*8+j;
            atomicAdd(&sh_sum[col],ts[j]);
            atomicAdd(&sh_sq[col],tq[j]);
            atomicMax(&sh_max[col],fkey(tm[j]));
        }
    __syncthreads();
    if(tid<128){
        atomicAdd(&g_s3[tid],(double)sh_sum[tid]);
        atomicAdd(&g_q3[tid],(double)sh_sq[tid]);
        d_m3[(size_t)blk*128+tid]=finv(sh_max[tid]);
    }
}

__global__ void final_kernel(float* __restrict__ outf){
    __shared__ float t[32][33];
    int b=blockIdx.z, o0=blockIdx.y*32, p0=blockIdx.x*32;
#pragma unroll
    for(int k=0;k<32;k+=8){
        int p=p0+threadIdx.y+k, o=o0+threadIdx.x;
        float v=d_m3[((size_t)b*PP+p)*128+o];
        t[threadIdx.y+k][threadIdx.x]=fmaxf(fmaf(g_a3[o],v,g_c3[o]),0.f);
    }
    __syncthreads();
#pragma unroll
    for(int k=0;k<32;k+=8){
        int o=o0+threadIdx.y+k;
        outf[((size_t)b*128+o)*PP+p0+threadIdx.x]=t[threadIdx.x][threadIdx.y+k];
    }
}

extern "C" void kernel_launch(void* const* d_in, const int* in_sizes, int n_in,
                              void* d_out, int out_size){
    const float* xyz =(const float*)d_in[0];
    const float* feat=(const float*)d_in[1];
    const float* W1  =(const float*)d_in[2];
    const float* g1  =(const float*)d_in[3];
    const float* b1  =(const float*)d_in[4];
    const float* W2  =(const float*)d_in[5];
    const float* g2  =(const float*)d_in[6];
    const float* b2  =(const float*)d_in[7];
    const float* W3  =(const float*)d_in[8];
    const float* g3  =(const float*)d_in[9];
    const float* b3  =(const float*)d_in[10];
    float* out=(float*)d_out;
    float* out_newxyz=out;
    float* out_feat  =out+(size_t)BB*PP*3;

    zero_stats<<<1,128>>>();
    {
        dim3 g(NN/32, CC/32, BB), b(32,8);
        transpose_feat<<<g,b>>>(feat);
    }
    {
        dim3 g(NN/256, BB);
        xyz_soa<<<g,256>>>(xyz);
    }
    fps_kernel<<<BB,1024>>>(xyz, out_newxyz);
    ballq_kernel<<<(BB*PP)/4,128>>>();
    gemm_l1<<<NROWS/64,256>>>(W1);
    mkscale_kernel<<<1,128>>>(g1,b1,1,64);
    gemm_l2<<<NROWS/64,256>>>(W2);
    mkscale_kernel<<<1,128>>>(g2,b2,2,64);
    gemm_l3<<<NROWS/32,256>>>(W3);
    mkscale_kernel<<<1,128>>>(g3,b3,3,128);
    {
        dim3 g(PP/32, 128/32, BB), b(32,8);
        final_kernel<<<g,b>>>(out_feat);
    }
}

// round 9
// speedup vs baseline: 1.6936x; 1.1008x over previous
#include <cuda_runtime.h>
#include <math.h>

#define BB 16
#define NN 4096
#define CC 64
#define PP 1024
#define SS 32
#define NROWS (BB*PP*SS)   // 524288

__device__ float  d_featT[(size_t)BB*NN*CC];
__device__ float  d_xyzT[(size_t)BB*3*NN];
__device__ float  d_newxyz[BB*PP*3];
__device__ int    d_idx[BB*PP*SS];
__device__ float  d_y1[(size_t)NROWS*64];
__device__ float  d_y2[(size_t)NROWS*64];
__device__ float  d_m3[(size_t)BB*PP*128];
__device__ double g_s1[64], g_q1[64], g_s2[64], g_q2[64], g_s3[128], g_q3[128];
__device__ float  g_a1[64], g_c1[64], g_a2[64], g_c2[64], g_a3[128], g_c3[128];

__device__ __forceinline__ float sqdist(float ax,float ay,float az,float bx,float by,float bz){
    float dx=__fsub_rn(ax,bx), dy=__fsub_rn(ay,by), dz=__fsub_rn(az,bz);
    return __fadd_rn(__fadd_rn(__fmul_rn(dx,dx),__fmul_rn(dy,dy)),__fmul_rn(dz,dz));
}
__device__ __forceinline__ unsigned fkey(float f){
    unsigned u=__float_as_uint(f); return (u&0x80000000u)?~u:(u|0x80000000u);
}
__device__ __forceinline__ float finv(unsigned k){
    unsigned u=(k&0x80000000u)?(k&0x7fffffffu):~k; return __uint_as_float(u);
}

__global__ void zero_stats(){
    int t=threadIdx.x;
    if(t<64){g_s1[t]=0.0;g_q1[t]=0.0;g_s2[t]=0.0;g_q2[t]=0.0;}
    if(t<128){g_s3[t]=0.0;g_q3[t]=0.0;}
}

__global__ void transpose_feat(const float* __restrict__ f){
    __shared__ float t[32][33];
    int b=blockIdx.z, c0=blockIdx.y*32, n0=blockIdx.x*32;
    const float* src=f+((size_t)b*CC+c0)*NN+n0;
#pragma unroll
    for(int k=0;k<32;k+=8)
        t[threadIdx.y+k][threadIdx.x]=src[(size_t)(threadIdx.y+k)*NN+threadIdx.x];
    __syncthreads();
    float* dst=d_featT+((size_t)b*NN+n0)*CC+c0;
#pragma unroll
    for(int k=0;k<32;k+=8)
        dst[(size_t)(threadIdx.y+k)*CC+threadIdx.x]=t[threadIdx.x][threadIdx.y+k];
}

__global__ __launch_bounds__(256) void xyz_soa(const float* __restrict__ xyz){
    __shared__ float s[768];
    int b=blockIdx.y, n0=blockIdx.x*256;
    const float* src=xyz+((size_t)b*NN+n0)*3;
    for(int k=threadIdx.x;k<768;k+=256) s[k]=src[k];
    __syncthreads();
    float* dst=d_xyzT+(size_t)b*3*NN;
    int n=n0+threadIdx.x;
    dst[n]      =s[threadIdx.x*3+0];
    dst[NN+n]   =s[threadIdx.x*3+1];
    dst[2*NN+n] =s[threadIdx.x*3+2];
}

// FPS: 512 threads x 8 pts, REDUX argmax (value max, then min index)
__global__ __launch_bounds__(512,1) void fps_kernel(const float* __restrict__ xyz,
                                                    float* __restrict__ out_newxyz){
    int b=blockIdx.x, tid=threadIdx.x;
    int warp=tid>>5, lane=tid&31;
    const float* X=xyz+(size_t)b*NN*3;
    float px[8],py[8],pz[8],dd[8];
#pragma unroll
    for(int j=0;j<8;j++){
        int p=tid+j*512;
        px[j]=X[p*3+0]; py[j]=X[p*3+1]; pz[j]=X[p*3+2]; dd[j]=1e10f;
    }
    __shared__ unsigned s_d[2][32];
    __shared__ unsigned s_i[2][32];
    if(tid<32){ s_d[0][tid]=0u; s_d[1][tid]=0u; s_i[0][tid]=0xFFFFFFFFu; s_i[1][tid]=0xFFFFFFFFu; }
    float lx=__ldg(&X[0]), ly=__ldg(&X[1]), lz=__ldg(&X[2]);
    if(tid==0){
        float* o1=d_newxyz+(size_t)b*PP*3; o1[0]=lx;o1[1]=ly;o1[2]=lz;
        float* o2=out_newxyz+(size_t)b*PP*3; o2[0]=lx;o2[1]=ly;o2[2]=lz;
    }
    __syncthreads();
    for(int it=1; it<PP; it++){
        int p=it&1;
#pragma unroll
        for(int j=0;j<8;j++){
            float d=sqdist(px[j],py[j],pz[j],lx,ly,lz);
            dd[j]=fminf(dd[j],d);
        }
        float m01=fmaxf(dd[0],dd[1]), m23=fmaxf(dd[2],dd[3]);
        float m45=fmaxf(dd[4],dd[5]), m67=fmaxf(dd[6],dd[7]);
        float m=fmaxf(fmaxf(m01,m23),fmaxf(m45,m67));
        unsigned cand=0xFFFFFFFFu;
#pragma unroll
        for(int j=7;j>=0;j--) if(dd[j]==m) cand=tid+(unsigned)(j*512);
        unsigned mb=__float_as_uint(m);
        unsigned wmax=__reduce_max_sync(0xffffffffu, mb);
        unsigned wi=__reduce_min_sync(0xffffffffu, (mb==wmax)?cand:0xFFFFFFFFu);
        if(lane==0){ s_d[p][warp]=wmax; s_i[p][warp]=wi; }
        __syncthreads();
        unsigned dv=s_d[p][lane];
        unsigned bmax=__reduce_max_sync(0xffffffffu, dv);
        unsigned widx=__reduce_min_sync(0xffffffffu, (dv==bmax)?s_i[p][lane]:0xFFFFFFFFu);
        lx=__ldg(&X[widx*3+0]);
        ly=__ldg(&X[widx*3+1]);
        lz=__ldg(&X[widx*3+2]);
        if(tid==0){
            float* o1=d_newxyz+((size_t)b*PP+it)*3; o1[0]=lx;o1[1]=ly;o1[2]=lz;
            float* o2=out_newxyz+((size_t)b*PP+it)*3; o2[0]=lx;o2[1]=ly;o2[2]=lz;
        }
    }
}

__global__ __launch_bounds__(128) void ballq_kernel(){
    int warp=blockIdx.x*4+(threadIdx.x>>5);
    int lane=threadIdx.x&31;
    int b=warp>>10;
    const float* Xx=d_xyzT+(size_t)b*3*NN;
    const float* Xy=Xx+NN;
    const float* Xz=Xx+2*NN;
    float cx=d_newxyz[warp*3+0], cy=d_newxyz[warp*3+1], cz=d_newxyz[warp*3+2];
    int* out=d_idx+(size_t)warp*SS;
    const float R2=0.04f;
    int cnt=0, firstIdx=-1;
    for(int base=0; base<NN && cnt<SS; base+=32){
        int n=base+lane;
        bool in=sqdist(cx,cy,cz,Xx[n],Xy[n],Xz[n])<R2;
        unsigned m=__ballot_sync(0xffffffffu,in);
        if(firstIdx<0 && m) firstIdx=base+__ffs(m)-1;
        if(in){
            int pos=cnt+__popc(m&((1u<<lane)-1u));
            if(pos<SS) out[pos]=n;
        }
        cnt+=__popc(m);
    }
    int written=cnt<SS?cnt:SS;
    if(lane>=written) out[lane]=firstIdx;
}

#define GEMM_BODY(Kc, SHX, SHW, ACC0, ACC1, R0, OG) \
_Pragma("unroll 4") \
for(int c=0;c<(Kc);c++){ \
    float h0=SHX[R0][c], h1=SHX[R0+1][c]; \
    const float4* wp=(const float4*)&SHW[c][(OG)*8]; \
    float4 wa=wp[0], wb=wp[1]; \
    ACC0[0]=fmaf(h0,wa.x,ACC0[0]); ACC1[0]=fmaf(h1,wa.x,ACC1[0]); \
    ACC0[1]=fmaf(h0,wa.y,ACC0[1]); ACC1[1]=fmaf(h1,wa.y,ACC1[1]); \
    ACC0[2]=fmaf(h0,wa.z,ACC0[2]); ACC1[2]=fmaf(h1,wa.z,ACC1[2]); \
    ACC0[3]=fmaf(h0,wa.w,ACC0[3]); ACC1[3]=fmaf(h1,wa.w,ACC1[3]); \
    ACC0[4]=fmaf(h0,wb.x,ACC0[4]); ACC1[4]=fmaf(h1,wb.x,ACC1[4]); \
    ACC0[5]=fmaf(h0,wb.y,ACC0[5]); ACC1[5]=fmaf(h1,wb.y,ACC1[5]); \
    ACC0[6]=fmaf(h0,wb.z,ACC0[6]); ACC1[6]=fmaf(h1,wb.z,ACC1[6]); \
    ACC0[7]=fmaf(h0,wb.w,ACC0[7]); ACC1[7]=fmaf(h1,wb.w,ACC1[7]); \
}

#define STORE2x8(DST, BASE, A0, A1, RS) \
    ((float4*)((DST)+(BASE)))[0]=make_float4(A0[0],A0[1],A0[2],A0[3]); \
    ((float4*)((DST)+(BASE)))[1]=make_float4(A0[4],A0[5],A0[6],A0[7]); \
    ((float4*)((DST)+(BASE)+(RS)))[0]=make_float4(A1[0],A1[1],A1[2],A1[3]); \
    ((float4*)((DST)+(BASE)+(RS)))[1]=make_float4(A1[4],A1[5],A1[6],A1[7]);

#define STATS_RED_64(TS,TQ) \
_Pragma("unroll") \
for(int j=0;j<8;j++){ \
    TS[j]+=__shfl_xor_sync(0xffffffffu,TS[j],8); \
    TQ[j]+=__shfl_xor_sync(0xffffffffu,TQ[j],8); \
    TS[j]+=__shfl_xor_sync(0xffffffffu,TS[j],16); \
    TQ[j]+=__shfl_xor_sync(0xffffffffu,TQ[j],16); \
}

__global__ __launch_bounds__(256) void gemm_l1(const float* __restrict__ W1){
    __shared__ float sh_h[64][68];
    __shared__ float sh_w[67][68];
    __shared__ float sh_sum[64], sh_sq[64];
    int tid=threadIdx.x, blk=blockIdx.x;
    for(int e=tid;e<64*67;e+=256){ int o=e/67, c=e-o*67; sh_w[c][o]=W1[e]; }
    if(tid<64){ sh_sum[tid]=0.f; sh_sq[tid]=0.f; }
    {
        int r=tid>>2, q=tid&3;
        int grp=blk*2+(r>>5);
        int b=grp>>10;
        int i=d_idx[(size_t)grp*SS+(r&31)];
        const float4* fr=(const float4*)(d_featT+((size_t)b*NN+i)*CC);
#pragma unroll
        for(int k=0;k<4;k++){
            float4 v=fr[q*4+k];
            int o0=3+q*16+k*4;
            sh_h[r][o0+0]=v.x; sh_h[r][o0+1]=v.y; sh_h[r][o0+2]=v.z; sh_h[r][o0+3]=v.w;
        }
        if(q==0){
            const float* xt=d_xyzT+(size_t)b*3*NN;
            const float* cp=d_newxyz+(size_t)grp*3;
            sh_h[r][0]=__fsub_rn(xt[i],      cp[0]);
            sh_h[r][1]=__fsub_rn(xt[NN+i],   cp[1]);
            sh_h[r][2]=__fsub_rn(xt[2*NN+i], cp[2]);
        }
    }
    __syncthreads();
    int og=tid&7, sp=tid>>3, r0=sp*2;
    float acc0[8]={0,0,0,0,0,0,0,0}, acc1[8]={0,0,0,0,0,0,0,0};
    GEMM_BODY(67, sh_h, sh_w, acc0, acc1, r0, og)
    size_t base=((size_t)blk*64+r0)*64+og*8;
    STORE2x8(d_y1, base, acc0, acc1, 64)
    float ts[8],tq[8];
#pragma unroll
    for(int j=0;j<8;j++){ ts[j]=acc0[j]+acc1[j]; tq[j]=acc0[j]*acc0[j]+acc1[j]*acc1[j]; }
    STATS_RED_64(ts,tq)
    int lane=tid&31;
    if(lane<8)
#pragma unroll
        for(int j=0;j<8;j++){
            atomicAdd(&sh_sum[lane*8+j],ts[j]);
            atomicAdd(&sh_sq[lane*8+j],tq[j]);
        }
    __syncthreads();
    if(tid<64){ atomicAdd(&g_s1[tid],(double)sh_sum[tid]); atomicAdd(&g_q1[tid],(double)sh_sq[tid]); }
}

__global__ void mkscale_kernel(const float* __restrict__ g, const float* __restrict__ bb,
                               int layer, int Cn){
    int o=threadIdx.x;
    if(o>=Cn) return;
    const double inv=1.0/(double)NROWS;
    double s,q;
    if(layer==1){s=g_s1[o];q=g_q1[o];}
    else if(layer==2){s=g_s2[o];q=g_q2[o];}
    else {s=g_s3[o];q=g_q3[o];}
    double m=s*inv, v=q*inv-m*m;
    double aa=(double)g[o]/sqrt(v+1e-5);
    float af=(float)aa, cf=(float)((double)bb[o]-m*aa);
    if(layer==1){g_a1[o]=af;g_c1[o]=cf;}
    else if(layer==2){g_a2[o]=af;g_c2[o]=cf;}
    else {g_a3[o]=af;g_c3[o]=cf;}
}

__global__ __launch_bounds__(256) void gemm_l2(const float* __restrict__ W2){
    __shared__ float sh_x[64][68];
    __shared__ float sh_w[64][68];
    __shared__ float sh_sum[64], sh_sq[64];
    int tid=threadIdx.x, blk=blockIdx.x;
    for(int e=tid;e<64*64;e+=256){ int o=e>>6, c=e&63; sh_w[c][o]=W2[e]; }
    if(tid<64){ sh_sum[tid]=0.f; sh_sq[tid]=0.f; }
    {
        int r=tid>>2, q=tid&3;
        const float4* src=(const float4*)(d_y1+((size_t)blk*64+r)*64+q*16);
#pragma unroll
        for(int k=0;k<4;k++){
            float4 v=src[k];
            int c0=q*16+k*4;
            sh_x[r][c0+0]=fmaxf(fmaf(g_a1[c0+0],v.x,g_c1[c0+0]),0.f);
            sh_x[r][c0+1]=fmaxf(fmaf(g_a1[c0+1],v.y,g_c1[c0+1]),0.f);
            sh_x[r][c0+2]=fmaxf(fmaf(g_a1[c0+2],v.z,g_c1[c0+2]),0.f);
            sh_x[r][c0+3]=fmaxf(fmaf(g_a1[c0+3],v.w,g_c1[c0+3]),0.f);
        }
    }
    __syncthreads();
    int og=tid&7, sp=tid>>3, r0=sp*2;
    float acc0[8]={0,0,0,0,0,0,0,0}, acc1[8]={0,0,0,0,0,0,0,0};
    GEMM_BODY(64, sh_x, sh_w, acc0, acc1, r0, og)
    size_t base=((size_t)blk*64+r0)*64+og*8;
    STORE2x8(d_y2, base, acc0, acc1, 64)
    float ts[8],tq[8];
#pragma unroll
    for(int j=0;j<8;j++){ ts[j]=acc0[j]+acc1[j]; tq[j]=acc0[j]*acc0[j]+acc1[j]*acc1[j]; }
    STATS_RED_64(ts,tq)
    int lane=tid&31;
    if(lane<8)
#pragma unroll
        for(int j=0;j<8;j++){
            atomicAdd(&sh_sum[lane*8+j],ts[j]);
            atomicAdd(&sh_sq[lane*8+j],tq[j]);
        }
    __syncthreads();
    if(tid<64){ atomicAdd(&g_s2[tid],(double)sh_sum[tid]); atomicAdd(&g_q2[tid],(double)sh_sq[tid]); }
}

// layer3: 512 threads, 64 rows (2 pool-groups) per block
__global__ __launch_bounds__(512) void gemm_l3(const float* __restrict__ W3){
    __shared__ float sh_x[64][68];
    __shared__ float sh_w[64][132];
    __shared__ float sh_sum[128], sh_sq[128];
    __shared__ unsigned sh_max[2][128];
    int tid=threadIdx.x, blk=blockIdx.x;   // blk = 2 groups (64 rows)
    for(int e=tid;e<128*64;e+=512){ int o=e>>6, c=e&63; sh_w[c][o]=W3[e]; }
    if(tid<128){ sh_sum[tid]=0.f; sh_sq[tid]=0.f; }
    if(tid<256) sh_max[tid>>7][tid&127]=0u;
    {
        int r=tid>>3, q=tid&7;
        const float4* src=(const float4*)(d_y2+((size_t)blk*64+r)*64+q*8);
#pragma unroll
        for(int k=0;k<2;k++){
            float4 v=src[k];
            int c0=q*8+k*4;
            sh_x[r][c0+0]=fmaxf(fmaf(g_a2[c0+0],v.x,g_c2[c0+0]),0.f);
            sh_x[r][c0+1]=fmaxf(fmaf(g_a2[c0+1],v.y,g_c2[c0+1]),0.f);
            sh_x[r][c0+2]=fmaxf(fmaf(g_a2[c0+2],v.z,g_c2[c0+2]),0.f);
            sh_x[r][c0+3]=fmaxf(fmaf(g_a2[c0+3],v.w,g_c2[c0+3]),0.f);
        }
    }
    __syncthreads();
    int og=tid&15, sp=tid>>4, r0=sp*2;   // sp 0..31 -> rows 0..63
    float acc0[8]={0,0,0,0,0,0,0,0}, acc1[8]={0,0,0,0,0,0,0,0};
    GEMM_BODY(64, sh_x, sh_w, acc0, acc1, r0, og)
    float ts[8],tq[8],tm[8];
#pragma unroll
    for(int j=0;j<8;j++){
        ts[j]=acc0[j]+acc1[j];
        tq[j]=acc0[j]*acc0[j]+acc1[j]*acc1[j];
        tm[j]=fmaxf(acc0[j],acc1[j]);
    }
    // warp covers rows 4w..4w+3 (same pool group); combine lane-pairs over bit 4
#pragma unroll
    for(int j=0;j<8;j++){
        ts[j]+=__shfl_xor_sync(0xffffffffu,ts[j],16);
        tq[j]+=__shfl_xor_sync(0xffffffffu,tq[j],16);
        tm[j]=fmaxf(tm[j],__shfl_xor_sync(0xffffffffu,tm[j],16));
    }
    int lane=tid&31;
    int grp=tid>>8;   // 0 for rows 0..31 (warps 0-7), 1 for rows 32..63
    if(lane<16)
#pragma unroll
        for(int j=0;j<8;j++){
            int col=lane*8+j;
            atomicAdd(&sh_sum[col],ts[j]);
            atomicAdd(&sh_sq[col],tq[j]);
            atomicMax(&sh_max[grp][col],fkey(tm[j]));
        }
    __syncthreads();
    if(tid<128){
        atomicAdd(&g_s3[tid],(double)sh_sum[tid]);
        atomicAdd(&g_q3[tid],(double)sh_sq[tid]);
    }
    if(tid<256)
        d_m3[((size_t)blk*2+(tid>>7))*128+(tid&127)]=finv(sh_max[tid>>7][tid&127]);
}

__global__ void final_kernel(float* __restrict__ outf){
    __shared__ float t[32][33];
    int b=blockIdx.z, o0=blockIdx.y*32, p0=blockIdx.x*32;
#pragma unroll
    for(int k=0;k<32;k+=8){
        int p=p0+threadIdx.y+k, o=o0+threadIdx.x;
        float v=d_m3[((size_t)b*PP+p)*128+o];
        t[threadIdx.y+k][threadIdx.x]=fmaxf(fmaf(g_a3[o],v,g_c3[o]),0.f);
    }
    __syncthreads();
#pragma unroll
    for(int k=0;k<32;k+=8){
        int o=o0+threadIdx.y+k;
        outf[((size_t)b*128+o)*PP+p0+threadIdx.x]=t[threadIdx.x][threadIdx.y+k];
    }
}

extern "C" void kernel_launch(void* const* d_in, const int* in_sizes, int n_in,
                              void* d_out, int out_size){
    const float* xyz =(const float*)d_in[0];
    const float* feat=(const float*)d_in[1];
    const float* W1  =(const float*)d_in[2];
    const float* g1  =(const float*)d_in[3];
    const float* b1  =(const float*)d_in[4];
    const float* W2  =(const float*)d_in[5];
    const float* g2  =(const float*)d_in[6];
    const float* b2  =(const float*)d_in[7];
    const float* W3  =(const float*)d_in[8];
    const float* g3  =(const float*)d_in[9];
    const float* b3  =(const float*)d_in[10];
    float* out=(float*)d_out;
    float* out_newxyz=out;
    float* out_feat  =out+(size_t)BB*PP*3;

    zero_stats<<<1,128>>>();
    {
        dim3 g(NN/32, CC/32, BB), b(32,8);
        transpose_feat<<<g,b>>>(feat);
    }
    {
        dim3 g(NN/256, BB);
        xyz_soa<<<g,256>>>(xyz);
    }
    fps_kernel<<<BB,512>>>(xyz, out_newxyz);
    ballq_kernel<<<(BB*PP)/4,128>>>();
    gemm_l1<<<NROWS/64,256>>>(W1);
    mkscale_kernel<<<1,128>>>(g1,b1,1,64);
    gemm_l2<<<NROWS/64,256>>>(W2);
    mkscale_kernel<<<1,128>>>(g2,b2,2,64);
    gemm_l3<<<NROWS/64,512>>>(W3);
    mkscale_kernel<<<1,128>>>(g3,b3,3,128);
    {
        dim3 g(PP/32, 128/32, BB), b(32,8);
        final_kernel<<<g,b>>>(out_feat);
    }
}

// round 10
// speedup vs baseline: 1.7347x; 1.0243x over previous
#include <cuda_runtime.h>
#include <math.h>

#define BB 16
#define NN 4096
#define CC 64
#define PP 1024
#define SS 32
#define NROWS (BB*PP*SS)   // 524288

__device__ float  d_featT[(size_t)BB*NN*CC];
__device__ float  d_xyzT[(size_t)BB*3*NN];
__device__ float  d_newxyz[BB*PP*3];
__device__ int    d_idx[BB*PP*SS];
__device__ float  d_y1[(size_t)NROWS*64];
__device__ float  d_y2[(size_t)NROWS*64];
__device__ float  d_m3[(size_t)BB*PP*128];
__device__ double g_s1[64], g_q1[64], g_s2[64], g_q2[64], g_s3[128], g_q3[128];
__device__ float  g_a1[64], g_c1[64], g_a2[64], g_c2[64], g_a3[128], g_c3[128];

__device__ __forceinline__ float sqdist(float ax,float ay,float az,float bx,float by,float bz){
    float dx=__fsub_rn(ax,bx), dy=__fsub_rn(ay,by), dz=__fsub_rn(az,bz);
    return __fadd_rn(__fadd_rn(__fmul_rn(dx,dx),__fmul_rn(dy,dy)),__fmul_rn(dz,dz));
}
__device__ __forceinline__ unsigned fkey(float f){
    unsigned u=__float_as_uint(f); return (u&0x80000000u)?~u:(u|0x80000000u);
}
__device__ __forceinline__ float finv(unsigned k){
    unsigned u=(k&0x80000000u)?(k&0x7fffffffu):~k; return __uint_as_float(u);
}
__device__ __forceinline__ unsigned long long pk2(float a,float b){
    unsigned long long r; asm("mov.b64 %0,{%1,%2};" : "=l"(r) : "f"(a),"f"(b)); return r;
}
__device__ __forceinline__ void upk2(unsigned long long v,float&a,float&b){
    asm("mov.b64 {%0,%1},%2;" : "=f"(a),"=f"(b) : "l"(v));
}
__device__ __forceinline__ unsigned long long add2(unsigned long long a,unsigned long long b){
    unsigned long long r; asm("add.rn.f32x2 %0,%1,%2;" : "=l"(r) : "l"(a),"l"(b)); return r;
}
__device__ __forceinline__ unsigned long long mul2(unsigned long long a,unsigned long long b){
    unsigned long long r; asm("mul.rn.f32x2 %0,%1,%2;" : "=l"(r) : "l"(a),"l"(b)); return r;
}

__global__ void zero_stats(){
    int t=threadIdx.x;
    if(t<64){g_s1[t]=0.0;g_q1[t]=0.0;g_s2[t]=0.0;g_q2[t]=0.0;}
    if(t<128){g_s3[t]=0.0;g_q3[t]=0.0;}
}

__global__ void transpose_feat(const float* __restrict__ f){
    __shared__ float t[32][33];
    int b=blockIdx.z, c0=blockIdx.y*32, n0=blockIdx.x*32;
    const float* src=f+((size_t)b*CC+c0)*NN+n0;
#pragma unroll
    for(int k=0;k<32;k+=8)
        t[threadIdx.y+k][threadIdx.x]=src[(size_t)(threadIdx.y+k)*NN+threadIdx.x];
    __syncthreads();
    float* dst=d_featT+((size_t)b*NN+n0)*CC+c0;
#pragma unroll
    for(int k=0;k<32;k+=8)
        dst[(size_t)(threadIdx.y+k)*CC+threadIdx.x]=t[threadIdx.x][threadIdx.y+k];
}

__global__ __launch_bounds__(256) void xyz_soa(const float* __restrict__ xyz){
    __shared__ float s[768];
    int b=blockIdx.y, n0=blockIdx.x*256;
    const float* src=xyz+((size_t)b*NN+n0)*3;
    for(int k=threadIdx.x;k<768;k+=256) s[k]=src[k];
    __syncthreads();
    float* dst=d_xyzT+(size_t)b*3*NN;
    int n=n0+threadIdx.x;
    dst[n]      =s[threadIdx.x*3+0];
    dst[NN+n]   =s[threadIdx.x*3+1];
    dst[2*NN+n] =s[threadIdx.x*3+2];
}

// FPS: 512 thr x 8 pts, packed f32x2 distance math, REDUX argmax
__global__ __launch_bounds__(512,1) void fps_kernel(const float* __restrict__ xyz,
                                                    float* __restrict__ out_newxyz){
    int b=blockIdx.x, tid=threadIdx.x;
    int warp=tid>>5, lane=tid&31;
    const float* X=xyz+(size_t)b*NN*3;
    unsigned long long px2[4],py2[4],pz2[4];
    float dd[8];
#pragma unroll
    for(int jj=0;jj<4;jj++){
        int p0=tid+(2*jj)*512, p1=tid+(2*jj+1)*512;
        px2[jj]=pk2(X[p0*3+0],X[p1*3+0]);
        py2[jj]=pk2(X[p0*3+1],X[p1*3+1]);
        pz2[jj]=pk2(X[p0*3+2],X[p1*3+2]);
        dd[2*jj]=1e10f; dd[2*jj+1]=1e10f;
    }
    __shared__ unsigned s_d[2][32];
    __shared__ unsigned s_i[2][32];
    if(tid<32){ s_d[0][tid]=0u; s_d[1][tid]=0u; s_i[0][tid]=0xFFFFFFFFu; s_i[1][tid]=0xFFFFFFFFu; }
    float lx=__ldg(&X[0]), ly=__ldg(&X[1]), lz=__ldg(&X[2]);
    if(tid==0){
        float* o1=d_newxyz+(size_t)b*PP*3; o1[0]=lx;o1[1]=ly;o1[2]=lz;
        float* o2=out_newxyz+(size_t)b*PP*3; o2[0]=lx;o2[1]=ly;o2[2]=lz;
    }
    __syncthreads();
    for(int it=1; it<PP; it++){
        int p=it&1;
        unsigned long long nx=pk2(-lx,-lx), ny=pk2(-ly,-ly), nz=pk2(-lz,-lz);
#pragma unroll
        for(int jj=0;jj<4;jj++){
            unsigned long long dx=add2(px2[jj],nx);
            unsigned long long dy=add2(py2[jj],ny);
            unsigned long long dz=add2(pz2[jj],nz);
            unsigned long long s=add2(add2(mul2(dx,dx),mul2(dy,dy)),mul2(dz,dz));
            float d0,d1; upk2(s,d0,d1);
            dd[2*jj]=fminf(dd[2*jj],d0);
            dd[2*jj+1]=fminf(dd[2*jj+1],d1);
        }
        float m01=fmaxf(dd[0],dd[1]), m23=fmaxf(dd[2],dd[3]);
        float m45=fmaxf(dd[4],dd[5]), m67=fmaxf(dd[6],dd[7]);
        float m=fmaxf(fmaxf(m01,m23),fmaxf(m45,m67));
        unsigned cand=0xFFFFFFFFu;
#pragma unroll
        for(int j=7;j>=0;j--) if(dd[j]==m) cand=tid+(unsigned)(j*512);
        unsigned mb=__float_as_uint(m);
        unsigned wmax=__reduce_max_sync(0xffffffffu, mb);
        unsigned wi=__reduce_min_sync(0xffffffffu, (mb==wmax)?cand:0xFFFFFFFFu);
        if(lane==0){ s_d[p][warp]=wmax; s_i[p][warp]=wi; }
        __syncthreads();
        unsigned dv=s_d[p][lane];
        unsigned bmax=__reduce_max_sync(0xffffffffu, dv);
        unsigned widx=__reduce_min_sync(0xffffffffu, (dv==bmax)?s_i[p][lane]:0xFFFFFFFFu);
        lx=__ldg(&X[widx*3+0]);
        ly=__ldg(&X[widx*3+1]);
        lz=__ldg(&X[widx*3+2]);
        if(tid==0){
            float* o1=d_newxyz+((size_t)b*PP+it)*3; o1[0]=lx;o1[1]=ly;o1[2]=lz;
            float* o2=out_newxyz+((size_t)b*PP+it)*3; o2[0]=lx;o2[1]=ly;o2[2]=lz;
        }
    }
}

__global__ __launch_bounds__(128) void ballq_kernel(){
    int warp=blockIdx.x*4+(threadIdx.x>>5);
    int lane=threadIdx.x&31;
    int b=warp>>10;
    const float* Xx=d_xyzT+(size_t)b*3*NN;
    const float* Xy=Xx+NN;
    const float* Xz=Xx+2*NN;
    float cx=d_newxyz[warp*3+0], cy=d_newxyz[warp*3+1], cz=d_newxyz[warp*3+2];
    int* out=d_idx+(size_t)warp*SS;
    const float R2=0.04f;
    int cnt=0, firstIdx=-1;
    for(int base=0; base<NN && cnt<SS; base+=32){
        int n=base+lane;
        bool in=sqdist(cx,cy,cz,Xx[n],Xy[n],Xz[n])<R2;
        unsigned m=__ballot_sync(0xffffffffu,in);
        if(firstIdx<0 && m) firstIdx=base+__ffs(m)-1;
        if(in){
            int pos=cnt+__popc(m&((1u<<lane)-1u));
            if(pos<SS) out[pos]=n;
        }
        cnt+=__popc(m);
    }
    int written=cnt<SS?cnt:SS;
    if(lane>=written) out[lane]=firstIdx;
}

#define GEMM_BODY(Kc, SHX, SHW, ACC0, ACC1, R0, OG) \
_Pragma("unroll 4") \
for(int c=0;c<(Kc);c++){ \
    float h0=SHX[R0][c], h1=SHX[R0+1][c]; \
    const float4* wp=(const float4*)&SHW[c][(OG)*8]; \
    float4 wa=wp[0], wb=wp[1]; \
    ACC0[0]=fmaf(h0,wa.x,ACC0[0]); ACC1[0]=fmaf(h1,wa.x,ACC1[0]); \
    ACC0[1]=fmaf(h0,wa.y,ACC0[1]); ACC1[1]=fmaf(h1,wa.y,ACC1[1]); \
    ACC0[2]=fmaf(h0,wa.z,ACC0[2]); ACC1[2]=fmaf(h1,wa.z,ACC1[2]); \
    ACC0[3]=fmaf(h0,wa.w,ACC0[3]); ACC1[3]=fmaf(h1,wa.w,ACC1[3]); \
    ACC0[4]=fmaf(h0,wb.x,ACC0[4]); ACC1[4]=fmaf(h1,wb.x,ACC1[4]); \
    ACC0[5]=fmaf(h0,wb.y,ACC0[5]); ACC1[5]=fmaf(h1,wb.y,ACC1[5]); \
    ACC0[6]=fmaf(h0,wb.z,ACC0[6]); ACC1[6]=fmaf(h1,wb.z,ACC1[6]); \
    ACC0[7]=fmaf(h0,wb.w,ACC0[7]); ACC1[7]=fmaf(h1,wb.w,ACC1[7]); \
}

#define STORE2x8(DST, BASE, A0, A1, RS) \
    ((float4*)((DST)+(BASE)))[0]=make_float4(A0[0],A0[1],A0[2],A0[3]); \
    ((float4*)((DST)+(BASE)))[1]=make_float4(A0[4],A0[5],A0[6],A0[7]); \
    ((float4*)((DST)+(BASE)+(RS)))[0]=make_float4(A1[0],A1[1],A1[2],A1[3]); \
    ((float4*)((DST)+(BASE)+(RS)))[1]=make_float4(A1[4],A1[5],A1[6],A1[7]);

#define STATS_RED_64(TS,TQ) \
_Pragma("unroll") \
for(int j=0;j<8;j++){ \
    TS[j]+=__shfl_xor_sync(0xffffffffu,TS[j],8); \
    TQ[j]+=__shfl_xor_sync(0xffffffffu,TQ[j],8); \
    TS[j]+=__shfl_xor_sync(0xffffffffu,TS[j],16); \
    TQ[j]+=__shfl_xor_sync(0xffffffffu,TQ[j],16); \
}

// l1/l2 dynamic smem: sh_x 128x68 | sh_w 68x68 | sum 64 | sq 64
#define SMEM_L12 ((128*68 + 68*68 + 128)*4)
// l3 dynamic smem: sh_x 128x68 | sh_w 64x132 | sum 128 | sq 128 | max 4x128
#define SMEM_L3  ((128*68 + 64*132 + 256 + 512)*4)

// layer1: 512 threads, 128 rows/block; fused gather + GEMM + stats
__global__ __launch_bounds__(512) void gemm_l1(const float* __restrict__ W1){
    extern __shared__ float dyn[];
    float (*sh_h)[68]=(float(*)[68])dyn;
    float (*sh_w)[68]=(float(*)[68])(dyn+128*68);
    float* sh_sum=dyn+128*68+68*68;
    float* sh_sq =sh_sum+64;
    int tid=threadIdx.x, blk=blockIdx.x;
    for(int e=tid;e<64*67;e+=512){ int o=e/67, c=e-o*67; sh_w[c][o]=W1[e]; }
    if(tid<64){ sh_sum[tid]=0.f; sh_sq[tid]=0.f; }
    {
        int r=tid>>2, q=tid&3;          // r 0..127
        int grp=blk*4+(r>>5);
        int b=grp>>10;
        int i=d_idx[(size_t)grp*SS+(r&31)];
        const float4* fr=(const float4*)(d_featT+((size_t)b*NN+i)*CC);
#pragma unroll
        for(int k=0;k<4;k++){
            float4 v=fr[q*4+k];
            int o0=3+q*16+k*4;
            sh_h[r][o0+0]=v.x; sh_h[r][o0+1]=v.y; sh_h[r][o0+2]=v.z; sh_h[r][o0+3]=v.w;
        }
        if(q==0){
            const float* xt=d_xyzT+(size_t)b*3*NN;
            const float* cp=d_newxyz+(size_t)grp*3;
            sh_h[r][0]=__fsub_rn(xt[i],      cp[0]);
            sh_h[r][1]=__fsub_rn(xt[NN+i],   cp[1]);
            sh_h[r][2]=__fsub_rn(xt[2*NN+i], cp[2]);
        }
    }
    __syncthreads();
    int og=tid&7, sp=tid>>3, r0=sp*2;   // sp 0..63 -> rows 0..127
    float acc0[8]={0,0,0,0,0,0,0,0}, acc1[8]={0,0,0,0,0,0,0,0};
    GEMM_BODY(67, sh_h, sh_w, acc0, acc1, r0, og)
    size_t base=((size_t)blk*128+r0)*64+og*8;
    STORE2x8(d_y1, base, acc0, acc1, 64)
    float ts[8],tq[8];
#pragma unroll
    for(int j=0;j<8;j++){ ts[j]=acc0[j]+acc1[j]; tq[j]=acc0[j]*acc0[j]+acc1[j]*acc1[j]; }
    STATS_RED_64(ts,tq)
    int lane=tid&31;
    if(lane<8)
#pragma unroll
        for(int j=0;j<8;j++){
            atomicAdd(&sh_sum[lane*8+j],ts[j]);
            atomicAdd(&sh_sq[lane*8+j],tq[j]);
        }
    __syncthreads();
    if(tid<64){ atomicAdd(&g_s1[tid],(double)sh_sum[tid]); atomicAdd(&g_q1[tid],(double)sh_sq[tid]); }
}

__global__ void mkscale_kernel(const float* __restrict__ g, const float* __restrict__ bb,
                               int layer, int Cn){
    int o=threadIdx.x;
    if(o>=Cn) return;
    const double inv=1.0/(double)NROWS;
    double s,q;
    if(layer==1){s=g_s1[o];q=g_q1[o];}
    else if(layer==2){s=g_s2[o];q=g_q2[o];}
    else {s=g_s3[o];q=g_q3[o];}
    double m=s*inv, v=q*inv-m*m;
    double aa=(double)g[o]/sqrt(v+1e-5);
    float af=(float)aa, cf=(float)((double)bb[o]-m*aa);
    if(layer==1){g_a1[o]=af;g_c1[o]=cf;}
    else if(layer==2){g_a2[o]=af;g_c2[o]=cf;}
    else {g_a3[o]=af;g_c3[o]=cf;}
}

// layer2: 512 threads, 128 rows/block
__global__ __launch_bounds__(512) void gemm_l2(const float* __restrict__ W2){
    extern __shared__ float dyn[];
    float (*sh_x)[68]=(float(*)[68])dyn;
    float (*sh_w)[68]=(float(*)[68])(dyn+128*68);
    float* sh_sum=dyn+128*68+68*68;
    float* sh_sq =sh_sum+64;
    int tid=threadIdx.x, blk=blockIdx.x;
    for(int e=tid;e<64*64;e+=512){ int o=e>>6, c=e&63; sh_w[c][o]=W2[e]; }
    if(tid<64){ sh_sum[tid]=0.f; sh_sq[tid]=0.f; }
    {
        int r=tid>>2, q=tid&3;          // r 0..127
        const float4* src=(const float4*)(d_y1+((size_t)blk*128+r)*64+q*16);
#pragma unroll
        for(int k=0;k<4;k++){
            float4 v=src[k];
            int c0=q*16+k*4;
            sh_x[r][c0+0]=fmaxf(fmaf(g_a1[c0+0],v.x,g_c1[c0+0]),0.f);
            sh_x[r][c0+1]=fmaxf(fmaf(g_a1[c0+1],v.y,g_c1[c0+1]),0.f);
            sh_x[r][c0+2]=fmaxf(fmaf(g_a1[c0+2],v.z,g_c1[c0+2]),0.f);
            sh_x[r][c0+3]=fmaxf(fmaf(g_a1[c0+3],v.w,g_c1[c0+3]),0.f);
        }
    }
    __syncthreads();
    int og=tid&7, sp=tid>>3, r0=sp*2;
    float acc0[8]={0,0,0,0,0,0,0,0}, acc1[8]={0,0,0,0,0,0,0,0};
    GEMM_BODY(64, sh_x, sh_w, acc0, acc1, r0, og)
    size_t base=((size_t)blk*128+r0)*64+og*8;
    STORE2x8(d_y2, base, acc0, acc1, 64)
    float ts[8],tq[8];
#pragma unroll
    for(int j=0;j<8;j++){ ts[j]=acc0[j]+acc1[j]; tq[j]=acc0[j]*acc0[j]+acc1[j]*acc1[j]; }
    STATS_RED_64(ts,tq)
    int lane=tid&31;
    if(lane<8)
#pragma unroll
        for(int j=0;j<8;j++){
            atomicAdd(&sh_sum[lane*8+j],ts[j]);
            atomicAdd(&sh_sq[lane*8+j],tq[j]);
        }
    __syncthreads();
    if(tid<64){ atomicAdd(&g_s2[tid],(double)sh_sum[tid]); atomicAdd(&g_q2[tid],(double)sh_sq[tid]); }
}

// layer3: 1024 threads, 128 rows (4 pool-groups) per block
__global__ __launch_bounds__(1024) void gemm_l3(const float* __restrict__ W3){
    extern __shared__ float dyn[];
    float (*sh_x)[68] =(float(*)[68])dyn;
    float (*sh_w)[132]=(float(*)[132])(dyn+128*68);
    float* sh_sum=dyn+128*68+64*132;
    float* sh_sq =sh_sum+128;
    unsigned* sh_max=(unsigned*)(sh_sq+128);   // [4][128]
    int tid=threadIdx.x, blk=blockIdx.x;       // blk = 4 groups (128 rows)
    for(int e=tid;e<128*64;e+=1024){ int o=e>>6, c=e&63; sh_w[c][o]=W3[e]; }
    if(tid<128){ sh_sum[tid]=0.f; sh_sq[tid]=0.f; }
    if(tid<512) sh_max[tid]=0u;
    {
        int r=tid>>3, q=tid&7;          // r 0..127
        const float4* src=(const float4*)(d_y2+((size_t)blk*128+r)*64+q*8);
#pragma unroll
        for(int k=0;k<2;k++){
            float4 v=src[k];
            int c0=q*8+k*4;
            sh_x[r][c0+0]=fmaxf(fmaf(g_a2[c0+0],v.x,g_c2[c0+0]),0.f);
            sh_x[r][c0+1]=fmaxf(fmaf(g_a2[c0+1],v.y,g_c2[c0+1]),0.f);
            sh_x[r][c0+2]=fmaxf(fmaf(g_a2[c0+2],v.z,g_c2[c0+2]),0.f);
            sh_x[r][c0+3]=fmaxf(fmaf(g_a2[c0+3],v.w,g_c2[c0+3]),0.f);
        }
    }
    __syncthreads();
    int og=tid&15, sp=tid>>4, r0=sp*2;  // sp 0..63 -> rows 0..127
    float acc0[8]={0,0,0,0,0,0,0,0}, acc1[8]={0,0,0,0,0,0,0,0};
    GEMM_BODY(64, sh_x, sh_w, acc0, acc1, r0, og)
    float ts[8],tq[8],tm[8];
#pragma unroll
    for(int j=0;j<8;j++){
        ts[j]=acc0[j]+acc1[j];
        tq[j]=acc0[j]*acc0[j]+acc1[j]*acc1[j];
        tm[j]=fmaxf(acc0[j],acc1[j]);
    }
    // warp w covers rows 4w..4w+3 (one pool group); combine sp-pair over lane bit 4
#pragma unroll
    for(int j=0;j<8;j++){
        ts[j]+=__shfl_xor_sync(0xffffffffu,ts[j],16);
        tq[j]+=__shfl_xor_sync(0xffffffffu,tq[j],16);
        tm[j]=fmaxf(tm[j],__shfl_xor_sync(0xffffffffu,tm[j],16));
    }
    int lane=tid&31;
    int grp=tid>>8;   // 4 groups of 8 warps (32 rows each)
    if(lane<16)
#pragma unroll
        for(int j=0;j<8;j++){
            int col=lane*8+j;
            atomicAdd(&sh_sum[col],ts[j]);
            atomicAdd(&sh_sq[col],tq[j]);
            atomicMax(&sh_max[grp*128+col],fkey(tm[j]));
        }
    __syncthreads();
    if(tid<128){
        atomicAdd(&g_s3[tid],(double)sh_sum[tid]);
        atomicAdd(&g_q3[tid],(double)sh_sq[tid]);
    }
    if(tid<512)
        d_m3[((size_t)blk*4+(tid>>7))*128+(tid&127)]=finv(sh_max[tid]);
}

__global__ void final_kernel(float* __restrict__ outf){
    __shared__ float t[32][33];
    int b=blockIdx.z, o0=blockIdx.y*32, p0=blockIdx.x*32;
#pragma unroll
    for(int k=0;k<32;k+=8){
        int p=p0+threadIdx.y+k, o=o0+threadIdx.x;
        float v=d_m3[((size_t)b*PP+p)*128+o];
        t[threadIdx.y+k][threadIdx.x]=fmaxf(fmaf(g_a3[o],v,g_c3[o]),0.f);
    }
    __syncthreads();
#pragma unroll
    for(int k=0;k<32;k+=8){
        int o=o0+threadIdx.y+k;
        outf[((size_t)b*128+o)*PP+p0+threadIdx.x]=t[threadIdx.x][threadIdx.y+k];
    }
}

extern "C" void kernel_launch(void* const* d_in, const int* in_sizes, int n_in,
                              void* d_out, int out_size){
    const float* xyz =(const float*)d_in[0];
    const float* feat=(const float*)d_in[1];
    const float* W1  =(const float*)d_in[2];
    const float* g1  =(const float*)d_in[3];
    const float* b1  =(const float*)d_in[4];
    const float* W2  =(const float*)d_in[5];
    const float* g2  =(const float*)d_in[6];
    const float* b2  =(const float*)d_in[7];
    const float* W3  =(const float*)d_in[8];
    const float* g3  =(const float*)d_in[9];
    const float* b3  =(const float*)d_in[10];
    float* out=(float*)d_out;
    float* out_newxyz=out;
    float* out_feat  =out+(size_t)BB*PP*3;

    static int smem_set=0;
    if(!smem_set){
        cudaFuncSetAttribute(gemm_l1, cudaFuncAttributeMaxDynamicSharedMemorySize, SMEM_L12);
        cudaFuncSetAttribute(gemm_l2, cudaFuncAttributeMaxDynamicSharedMemorySize, SMEM_L12);
        cudaFuncSetAttribute(gemm_l3, cudaFuncAttributeMaxDynamicSharedMemorySize, SMEM_L3);
        smem_set=1;
    }

    zero_stats<<<1,128>>>();
    {
        dim3 g(NN/32, CC/32, BB), b(32,8);
        transpose_feat<<<g,b>>>(feat);
    }
    {
        dim3 g(NN/256, BB);
        xyz_soa<<<g,256>>>(xyz);
    }
    fps_kernel<<<BB,512>>>(xyz, out_newxyz);
    ballq_kernel<<<(BB*PP)/4,128>>>();
    gemm_l1<<<NROWS/128,512,SMEM_L12>>>(W1);
    mkscale_kernel<<<1,128>>>(g1,b1,1,64);
    gemm_l2<<<NROWS/128,512,SMEM_L12>>>(W2);
    mkscale_kernel<<<1,128>>>(g2,b2,2,64);
    gemm_l3<<<NROWS/128,1024,SMEM_L3>>>(W3);
    mkscale_kernel<<<1,128>>>(g3,b3,3,128);
    {
        dim3 g(PP/32, 128/32, BB), b(32,8);
        final_kernel<<<g,b>>>(out_feat);
    }
}

// round 11
// speedup vs baseline: 1.8794x; 1.0834x over previous
#include <cuda_runtime.h>
#include <math.h>

#define BB 16
#define NN 4096
#define CC 64
#define PP 1024
#define SS 32
#define NROWS (BB*PP*SS)   // 524288

__device__ float  d_featT[(size_t)BB*NN*CC];
__device__ float  d_xyzT[(size_t)BB*3*NN];
__device__ float  d_newxyz[BB*PP*3];
__device__ int    d_idx[BB*PP*SS];
__device__ float  d_y1[(size_t)NROWS*64];
__device__ float  d_y2[(size_t)NROWS*64];
__device__ float  d_m3[(size_t)BB*PP*128];
__device__ double g_s1[64], g_q1[64], g_s2[64], g_q2[64], g_s3[128], g_q3[128];
__device__ float  g_a1[64], g_c1[64], g_a2[64], g_c2[64], g_a3[128], g_c3[128];

__device__ __forceinline__ float sqdist(float ax,float ay,float az,float bx,float by,float bz){
    float dx=__fsub_rn(ax,bx), dy=__fsub_rn(ay,by), dz=__fsub_rn(az,bz);
    return __fadd_rn(__fadd_rn(__fmul_rn(dx,dx),__fmul_rn(dy,dy)),__fmul_rn(dz,dz));
}
__device__ __forceinline__ unsigned fkey(float f){
    unsigned u=__float_as_uint(f); return (u&0x80000000u)?~u:(u|0x80000000u);
}
__device__ __forceinline__ float finv(unsigned k){
    unsigned u=(k&0x80000000u)?(k&0x7fffffffu):~k; return __uint_as_float(u);
}
__device__ __forceinline__ unsigned long long pk2(float a,float b){
    unsigned long long r; asm("mov.b64 %0,{%1,%2};" : "=l"(r) : "f"(a),"f"(b)); return r;
}
__device__ __forceinline__ void upk2(unsigned long long v,float&a,float&b){
    asm("mov.b64 {%0,%1},%2;" : "=f"(a),"=f"(b) : "l"(v));
}
__device__ __forceinline__ unsigned long long add2(unsigned long long a,unsigned long long b){
    unsigned long long r; asm("add.rn.f32x2 %0,%1,%2;" : "=l"(r) : "l"(a),"l"(b)); return r;
}
__device__ __forceinline__ unsigned long long mul2(unsigned long long a,unsigned long long b){
    unsigned long long r; asm("mul.rn.f32x2 %0,%1,%2;" : "=l"(r) : "l"(a),"l"(b)); return r;
}
__device__ __forceinline__ unsigned f2tf(float f){
    unsigned r; asm("cvt.rna.tf32.f32 %0,%1;" : "=r"(r) : "f"(f)); return r;
}
__device__ __forceinline__ void mma_tf32(float* c, unsigned a0,unsigned a1,unsigned a2,unsigned a3,
                                         unsigned b0,unsigned b1){
    asm("mma.sync.aligned.m16n8k8.row.col.f32.tf32.tf32.f32 "
        "{%0,%1,%2,%3},{%4,%5,%6,%7},{%8,%9},{%0,%1,%2,%3};"
        : "+f"(c[0]),"+f"(c[1]),"+f"(c[2]),"+f"(c[3])
        : "r"(a0),"r"(a1),"r"(a2),"r"(a3),"r"(b0),"r"(b1));
}

__global__ void zero_stats(){
    int t=threadIdx.x;
    if(t<64){g_s1[t]=0.0;g_q1[t]=0.0;g_s2[t]=0.0;g_q2[t]=0.0;}
    if(t<128){g_s3[t]=0.0;g_q3[t]=0.0;}
}

__global__ void transpose_feat(const float* __restrict__ f){
    __shared__ float t[32][33];
    int b=blockIdx.z, c0=blockIdx.y*32, n0=blockIdx.x*32;
    const float* src=f+((size_t)b*CC+c0)*NN+n0;
#pragma unroll
    for(int k=0;k<32;k+=8)
        t[threadIdx.y+k][threadIdx.x]=src[(size_t)(threadIdx.y+k)*NN+threadIdx.x];
    __syncthreads();
    float* dst=d_featT+((size_t)b*NN+n0)*CC+c0;
#pragma unroll
    for(int k=0;k<32;k+=8)
        dst[(size_t)(threadIdx.y+k)*CC+threadIdx.x]=t[threadIdx.x][threadIdx.y+k];
}

__global__ __launch_bounds__(256) void xyz_soa(const float* __restrict__ xyz){
    __shared__ float s[768];
    int b=blockIdx.y, n0=blockIdx.x*256;
    const float* src=xyz+((size_t)b*NN+n0)*3;
    for(int k=threadIdx.x;k<768;k+=256) s[k]=src[k];
    __syncthreads();
    float* dst=d_xyzT+(size_t)b*3*NN;
    int n=n0+threadIdx.x;
    dst[n]      =s[threadIdx.x*3+0];
    dst[NN+n]   =s[threadIdx.x*3+1];
    dst[2*NN+n] =s[threadIdx.x*3+2];
}

__global__ __launch_bounds__(512,1) void fps_kernel(const float* __restrict__ xyz,
                                                    float* __restrict__ out_newxyz){
    int b=blockIdx.x, tid=threadIdx.x;
    int warp=tid>>5, lane=tid&31;
    const float* X=xyz+(size_t)b*NN*3;
    unsigned long long px2[4],py2[4],pz2[4];
    float dd[8];
#pragma unroll
    for(int jj=0;jj<4;jj++){
        int p0=tid+(2*jj)*512, p1=tid+(2*jj+1)*512;
        px2[jj]=pk2(X[p0*3+0],X[p1*3+0]);
        py2[jj]=pk2(X[p0*3+1],X[p1*3+1]);
        pz2[jj]=pk2(X[p0*3+2],X[p1*3+2]);
        dd[2*jj]=1e10f; dd[2*jj+1]=1e10f;
    }
    __shared__ unsigned s_d[2][32];
    __shared__ unsigned s_i[2][32];
    if(tid<32){ s_d[0][tid]=0u; s_d[1][tid]=0u; s_i[0][tid]=0xFFFFFFFFu; s_i[1][tid]=0xFFFFFFFFu; }
    float lx=__ldg(&X[0]), ly=__ldg(&X[1]), lz=__ldg(&X[2]);
    if(tid==0){
        float* o1=d_newxyz+(size_t)b*PP*3; o1[0]=lx;o1[1]=ly;o1[2]=lz;
        float* o2=out_newxyz+(size_t)b*PP*3; o2[0]=lx;o2[1]=ly;o2[2]=lz;
    }
    __syncthreads();
    for(int it=1; it<PP; it++){
        int p=it&1;
        unsigned long long nx=pk2(-lx,-lx), ny=pk2(-ly,-ly), nz=pk2(-lz,-lz);
#pragma unroll
        for(int jj=0;jj<4;jj++){
            unsigned long long dx=add2(px2[jj],nx);
            unsigned long long dy=add2(py2[jj],ny);
            unsigned long long dz=add2(pz2[jj],nz);
            unsigned long long s=add2(add2(mul2(dx,dx),mul2(dy,dy)),mul2(dz,dz));
            float d0,d1; upk2(s,d0,d1);
            dd[2*jj]=fminf(dd[2*jj],d0);
            dd[2*jj+1]=fminf(dd[2*jj+1],d1);
        }
        float m01=fmaxf(dd[0],dd[1]), m23=fmaxf(dd[2],dd[3]);
        float m45=fmaxf(dd[4],dd[5]), m67=fmaxf(dd[6],dd[7]);
        float m=fmaxf(fmaxf(m01,m23),fmaxf(m45,m67));
        unsigned cand=0xFFFFFFFFu;
#pragma unroll
        for(int j=7;j>=0;j--) if(dd[j]==m) cand=tid+(unsigned)(j*512);
        unsigned mb=__float_as_uint(m);
        unsigned wmax=__reduce_max_sync(0xffffffffu, mb);
        unsigned wi=__reduce_min_sync(0xffffffffu, (mb==wmax)?cand:0xFFFFFFFFu);
        if(lane==0){ s_d[p][warp]=wmax; s_i[p][warp]=wi; }
        __syncthreads();
        unsigned dv=s_d[p][lane];
        unsigned bmax=__reduce_max_sync(0xffffffffu, dv);
        unsigned widx=__reduce_min_sync(0xffffffffu, (dv==bmax)?s_i[p][lane]:0xFFFFFFFFu);
        lx=__ldg(&X[widx*3+0]);
        ly=__ldg(&X[widx*3+1]);
        lz=__ldg(&X[widx*3+2]);
        if(tid==0){
            float* o1=d_newxyz+((size_t)b*PP+it)*3; o1[0]=lx;o1[1]=ly;o1[2]=lz;
            float* o2=out_newxyz+((size_t)b*PP+it)*3; o2[0]=lx;o2[1]=ly;o2[2]=lz;
        }
    }
}

__global__ __launch_bounds__(128) void ballq_kernel(){
    int warp=blockIdx.x*4+(threadIdx.x>>5);
    int lane=threadIdx.x&31;
    int b=warp>>10;
    const float* Xx=d_xyzT+(size_t)b*3*NN;
    const float* Xy=Xx+NN;
    const float* Xz=Xx+2*NN;
    float cx=d_newxyz[warp*3+0], cy=d_newxyz[warp*3+1], cz=d_newxyz[warp*3+2];
    int* out=d_idx+(size_t)warp*SS;
    const float R2=0.04f;
    int cnt=0, firstIdx=-1;
    for(int base=0; base<NN && cnt<SS; base+=32){
        int n=base+lane;
        bool in=sqdist(cx,cy,cz,Xx[n],Xy[n],Xz[n])<R2;
        unsigned m=__ballot_sync(0xffffffffu,in);
        if(firstIdx<0 && m) firstIdx=base+__ffs(m)-1;
        if(in){
            int pos=cnt+__popc(m&((1u<<lane)-1u));
            if(pos<SS) out[pos]=n;
        }
        cnt+=__popc(m);
    }
    int written=cnt<SS?cnt:SS;
    if(lane>=written) out[lane]=firstIdx;
}

#define GEMM_BODY(Kc, SHX, SHW, ACC0, ACC1, R0, OG) \
_Pragma("unroll 4") \
for(int c=0;c<(Kc);c++){ \
    float h0=SHX[R0][c], h1=SHX[R0+1][c]; \
    const float4* wp=(const float4*)&SHW[c][(OG)*8]; \
    float4 wa=wp[0], wb=wp[1]; \
    ACC0[0]=fmaf(h0,wa.x,ACC0[0]); ACC1[0]=fmaf(h1,wa.x,ACC1[0]); \
    ACC0[1]=fmaf(h0,wa.y,ACC0[1]); ACC1[1]=fmaf(h1,wa.y,ACC1[1]); \
    ACC0[2]=fmaf(h0,wa.z,ACC0[2]); ACC1[2]=fmaf(h1,wa.z,ACC1[2]); \
    ACC0[3]=fmaf(h0,wa.w,ACC0[3]); ACC1[3]=fmaf(h1,wa.w,ACC1[3]); \
    ACC0[4]=fmaf(h0,wb.x,ACC0[4]); ACC1[4]=fmaf(h1,wb.x,ACC1[4]); \
    ACC0[5]=fmaf(h0,wb.y,ACC0[5]); ACC1[5]=fmaf(h1,wb.y,ACC1[5]); \
    ACC0[6]=fmaf(h0,wb.z,ACC0[6]); ACC1[6]=fmaf(h1,wb.z,ACC1[6]); \
    ACC0[7]=fmaf(h0,wb.w,ACC0[7]); ACC1[7]=fmaf(h1,wb.w,ACC1[7]); \
}

#define STORE2x8(DST, BASE, A0, A1, RS) \
    ((float4*)((DST)+(BASE)))[0]=make_float4(A0[0],A0[1],A0[2],A0[3]); \
    ((float4*)((DST)+(BASE)))[1]=make_float4(A0[4],A0[5],A0[6],A0[7]); \
    ((float4*)((DST)+(BASE)+(RS)))[0]=make_float4(A1[0],A1[1],A1[2],A1[3]); \
    ((float4*)((DST)+(BASE)+(RS)))[1]=make_float4(A1[4],A1[5],A1[6],A1[7]);

#define STATS_RED_64(TS,TQ) \
_Pragma("unroll") \
for(int j=0;j<8;j++){ \
    TS[j]+=__shfl_xor_sync(0xffffffffu,TS[j],8); \
    TQ[j]+=__shfl_xor_sync(0xffffffffu,TQ[j],8); \
    TS[j]+=__shfl_xor_sync(0xffffffffu,TS[j],16); \
    TQ[j]+=__shfl_xor_sync(0xffffffffu,TQ[j],16); \
}

#define SMEM_L12 ((128*68 + 68*68 + 128)*4)
#define SMEM_L2T ((128*68 + 64*68 + 128)*4)
#define SMEM_L3T ((128*68 + 128*68 + 256 + 512)*4)

// layer1: scalar FFMA (K=67 + gather), unchanged
__global__ __launch_bounds__(512) void gemm_l1(const float* __restrict__ W1){
    extern __shared__ float dyn[];
    float (*sh_h)[68]=(float(*)[68])dyn;
    float (*sh_w)[68]=(float(*)[68])(dyn+128*68);
    float* sh_sum=dyn+128*68+68*68;
    float* sh_sq =sh_sum+64;
    int tid=threadIdx.x, blk=blockIdx.x;
    for(int e=tid;e<64*67;e+=512){ int o=e/67, c=e-o*67; sh_w[c][o]=W1[e]; }
    if(tid<64){ sh_sum[tid]=0.f; sh_sq[tid]=0.f; }
    {
        int r=tid>>2, q=tid&3;
        int grp=blk*4+(r>>5);
        int b=grp>>10;
        int i=d_idx[(size_t)grp*SS+(r&31)];
        const float4* fr=(const float4*)(d_featT+((size_t)b*NN+i)*CC);
#pragma unroll
        for(int k=0;k<4;k++){
            float4 v=fr[q*4+k];
            int o0=3+q*16+k*4;
            sh_h[r][o0+0]=v.x; sh_h[r][o0+1]=v.y; sh_h[r][o0+2]=v.z; sh_h[r][o0+3]=v.w;
        }
        if(q==0){
            const float* xt=d_xyzT+(size_t)b*3*NN;
            const float* cp=d_newxyz+(size_t)grp*3;
            sh_h[r][0]=__fsub_rn(xt[i],      cp[0]);
            sh_h[r][1]=__fsub_rn(xt[NN+i],   cp[1]);
            sh_h[r][2]=__fsub_rn(xt[2*NN+i], cp[2]);
        }
    }
    __syncthreads();
    int og=tid&7, sp=tid>>3, r0=sp*2;
    float acc0[8]={0,0,0,0,0,0,0,0}, acc1[8]={0,0,0,0,0,0,0,0};
    GEMM_BODY(67, sh_h, sh_w, acc0, acc1, r0, og)
    size_t base=((size_t)blk*128+r0)*64+og*8;
    STORE2x8(d_y1, base, acc0, acc1, 64)
    float ts[8],tq[8];
#pragma unroll
    for(int j=0;j<8;j++){ ts[j]=acc0[j]+acc1[j]; tq[j]=acc0[j]*acc0[j]+acc1[j]*acc1[j]; }
    STATS_RED_64(ts,tq)
    int lane=tid&31;
    if(lane<8)
#pragma unroll
        for(int j=0;j<8;j++){
            atomicAdd(&sh_sum[lane*8+j],ts[j]);
            atomicAdd(&sh_sq[lane*8+j],tq[j]);
        }
    __syncthreads();
    if(tid<64){ atomicAdd(&g_s1[tid],(double)sh_sum[tid]); atomicAdd(&g_q1[tid],(double)sh_sq[tid]); }
}

__global__ void mkscale_kernel(const float* __restrict__ g, const float* __restrict__ bb,
                               int layer, int Cn){
    int o=threadIdx.x;
    if(o>=Cn) return;
    const double inv=1.0/(double)NROWS;
    double s,q;
    if(layer==1){s=g_s1[o];q=g_q1[o];}
    else if(layer==2){s=g_s2[o];q=g_q2[o];}
    else {s=g_s3[o];q=g_q3[o];}
    double m=s*inv, v=q*inv-m*m;
    double aa=(double)g[o]/sqrt(v+1e-5);
    float af=(float)aa, cf=(float)((double)bb[o]-m*aa);
    if(layer==1){g_a1[o]=af;g_c1[o]=cf;}
    else if(layer==2){g_a2[o]=af;g_c2[o]=cf;}
    else {g_a3[o]=af;g_c3[o]=cf;}
}

// layer2: tf32 mma, 512 threads, 128 rows/block; warp = M16 x N32
__global__ __launch_bounds__(512) void gemm_l2(const float* __restrict__ W2){
    extern __shared__ float dyn[];
    float (*sh_x)[68]=(float(*)[68])dyn;              // 128 x 68 (BN1+ReLU)
    float (*sh_w)[68]=(float(*)[68])(dyn+128*68);     // 64 x 68, raw W2 [n][k]
    float* sh_sum=dyn+128*68+64*68;
    float* sh_sq =sh_sum+64;
    int tid=threadIdx.x, blk=blockIdx.x;
    for(int e=tid;e<64*64;e+=512) sh_w[e>>6][e&63]=W2[e];
    if(tid<64){ sh_sum[tid]=0.f; sh_sq[tid]=0.f; }
    {
        int r=tid>>2, q=tid&3;
        const float4* src=(const float4*)(d_y1+((size_t)blk*128+r)*64+q*16);
#pragma unroll
        for(int k=0;k<4;k++){
            float4 v=src[k];
            int c0=q*16+k*4;
            sh_x[r][c0+0]=fmaxf(fmaf(g_a1[c0+0],v.x,g_c1[c0+0]),0.f);
            sh_x[r][c0+1]=fmaxf(fmaf(g_a1[c0+1],v.y,g_c1[c0+1]),0.f);
            sh_x[r][c0+2]=fmaxf(fmaf(g_a1[c0+2],v.z,g_c1[c0+2]),0.f);
            sh_x[r][c0+3]=fmaxf(fmaf(g_a1[c0+3],v.w,g_c1[c0+3]),0.f);
        }
    }
    __syncthreads();
    int w=tid>>5, lane=tid&31, g=lane>>2, t=lane&3;
    int mt=w&7, nh=w>>3;
    int r0=mt*16;
    float acc[4][4];
#pragma unroll
    for(int nt=0;nt<4;nt++){acc[nt][0]=0;acc[nt][1]=0;acc[nt][2]=0;acc[nt][3]=0;}
#pragma unroll
    for(int kt=0;kt<8;kt++){
        int k0=kt*8;
        unsigned a0=f2tf(sh_x[r0+g  ][k0+t  ]);
        unsigned a1=f2tf(sh_x[r0+g+8][k0+t  ]);
        unsigned a2=f2tf(sh_x[r0+g  ][k0+t+4]);
        unsigned a3=f2tf(sh_x[r0+g+8][k0+t+4]);
#pragma unroll
        for(int nt=0;nt<4;nt++){
            int n0=nh*32+nt*8;
            unsigned b0=f2tf(sh_w[n0+g][k0+t  ]);
            unsigned b1=f2tf(sh_w[n0+g][k0+t+4]);
            mma_tf32(acc[nt], a0,a1,a2,a3, b0,b1);
        }
    }
#pragma unroll
    for(int nt=0;nt<4;nt++){
        int n0=nh*32+nt*8;
        int col=n0+2*t;
        float2 v0; v0.x=acc[nt][0]; v0.y=acc[nt][1];
        float2 v1; v1.x=acc[nt][2]; v1.y=acc[nt][3];
        *(float2*)(d_y2+((size_t)blk*128+r0+g  )*64+col)=v0;
        *(float2*)(d_y2+((size_t)blk*128+r0+g+8)*64+col)=v1;
        float s0=acc[nt][0]+acc[nt][2], s1=acc[nt][1]+acc[nt][3];
        float q0=acc[nt][0]*acc[nt][0]+acc[nt][2]*acc[nt][2];
        float q1=acc[nt][1]*acc[nt][1]+acc[nt][3]*acc[nt][3];
#pragma unroll
        for(int off=4;off<32;off<<=1){
            s0+=__shfl_xor_sync(0xffffffffu,s0,off);
            s1+=__shfl_xor_sync(0xffffffffu,s1,off);
            q0+=__shfl_xor_sync(0xffffffffu,q0,off);
            q1+=__shfl_xor_sync(0xffffffffu,q1,off);
        }
        if(lane<4){
            atomicAdd(&sh_sum[col],s0); atomicAdd(&sh_sum[col+1],s1);
            atomicAdd(&sh_sq[col],q0);  atomicAdd(&sh_sq[col+1],q1);
        }
    }
    __syncthreads();
    if(tid<64){ atomicAdd(&g_s2[tid],(double)sh_sum[tid]); atomicAdd(&g_q2[tid],(double)sh_sq[tid]); }
}

// layer3: tf32 mma, 512 threads, 128 rows (4 pool-groups); warp = M16 x N64
__global__ __launch_bounds__(512) void gemm_l3(const float* __restrict__ W3){
    extern __shared__ float dyn[];
    float (*sh_x)[68]=(float(*)[68])dyn;               // 128 x 68 (BN2+ReLU)
    float (*sh_w)[68]=(float(*)[68])(dyn+128*68);      // 128 x 68, raw W3 [n][k]
    float* sh_sum=dyn+128*68+128*68;
    float* sh_sq =sh_sum+128;
    unsigned* sh_max=(unsigned*)(sh_sq+128);           // [4][128]
    int tid=threadIdx.x, blk=blockIdx.x;
    for(int e=tid;e<128*64;e+=512) sh_w[e>>6][e&63]=W3[e];
    if(tid<128){ sh_sum[tid]=0.f; sh_sq[tid]=0.f; }
    if(tid<512) sh_max[tid]=0u;
    {
        int r=tid>>2, q=tid&3;
        const float4* src=(const float4*)(d_y2+((size_t)blk*128+r)*64+q*16);
#pragma unroll
        for(int k=0;k<4;k++){
            float4 v=src[k];
            int c0=q*16+k*4;
            sh_x[r][c0+0]=fmaxf(fmaf(g_a2[c0+0],v.x,g_c2[c0+0]),0.f);
            sh_x[r][c0+1]=fmaxf(fmaf(g_a2[c0+1],v.y,g_c2[c0+1]),0.f);
            sh_x[r][c0+2]=fmaxf(fmaf(g_a2[c0+2],v.z,g_c2[c0+2]),0.f);
            sh_x[r][c0+3]=fmaxf(fmaf(g_a2[c0+3],v.w,g_c2[c0+3]),0.f);
        }
    }
    __syncthreads();
    int w=tid>>5, lane=tid&31, g=lane>>2, t=lane&3;
    int mt=w&7, nh=w>>3;
    int r0=mt*16;
    int grp=mt>>1;
    float acc[8][4];
#pragma unroll
    for(int nt=0;nt<8;nt++){acc[nt][0]=0;acc[nt][1]=0;acc[nt][2]=0;acc[nt][3]=0;}
#pragma unroll
    for(int kt=0;kt<8;kt++){
        int k0=kt*8;
        unsigned a0=f2tf(sh_x[r0+g  ][k0+t  ]);
        unsigned a1=f2tf(sh_x[r0+g+8][k0+t  ]);
        unsigned a2=f2tf(sh_x[r0+g  ][k0+t+4]);
        unsigned a3=f2tf(sh_x[r0+g+8][k0+t+4]);
#pragma unroll
        for(int nt=0;nt<8;nt++){
            int n0=nh*64+nt*8;
            unsigned b0=f2tf(sh_w[n0+g][k0+t  ]);
            unsigned b1=f2tf(sh_w[n0+g][k0+t+4]);
            mma_tf32(acc[nt], a0,a1,a2,a3, b0,b1);
        }
    }
#pragma unroll
    for(int nt=0;nt<8;nt++){
        int n0=nh*64+nt*8;
        int col=n0+2*t;
        float s0=acc[nt][0]+acc[nt][2], s1=acc[nt][1]+acc[nt][3];
        float q0=acc[nt][0]*acc[nt][0]+acc[nt][2]*acc[nt][2];
        float q1=acc[nt][1]*acc[nt][1]+acc[nt][3]*acc[nt][3];
        float m0=fmaxf(acc[nt][0],acc[nt][2]), m1=fmaxf(acc[nt][1],acc[nt][3]);
#pragma unroll
        for(int off=4;off<32;off<<=1){
            s0+=__shfl_xor_sync(0xffffffffu,s0,off);
            s1+=__shfl_xor_sync(0xffffffffu,s1,off);
            q0+=__shfl_xor_sync(0xffffffffu,q0,off);
            q1+=__shfl_xor_sync(0xffffffffu,q1,off);
            m0=fmaxf(m0,__shfl_xor_sync(0xffffffffu,m0,off));
            m1=fmaxf(m1,__shfl_xor_sync(0xffffffffu,m1,off));
        }
        if(lane<4){
            atomicAdd(&sh_sum[col],s0); atomicAdd(&sh_sum[col+1],s1);
            atomicAdd(&sh_sq[col],q0);  atomicAdd(&sh_sq[col+1],q1);
            atomicMax(&sh_max[grp*128+col],fkey(m0));
            atomicMax(&sh_max[grp*128+col+1],fkey(m1));
        }
    }
    __syncthreads();
    if(tid<128){
        atomicAdd(&g_s3[tid],(double)sh_sum[tid]);
        atomicAdd(&g_q3[tid],(double)sh_sq[tid]);
    }
    if(tid<512)
        d_m3[((size_t)blk*4+(tid>>7))*128+(tid&127)]=finv(sh_max[tid]);
}

__global__ void final_kernel(float* __restrict__ outf){
    __shared__ float t[32][33];
    int b=blockIdx.z, o0=blockIdx.y*32, p0=blockIdx.x*32;
#pragma unroll
    for(int k=0;k<32;k+=8){
        int p=p0+threadIdx.y+k, o=o0+threadIdx.x;
        float v=d_m3[((size_t)b*PP+p)*128+o];
        t[threadIdx.y+k][threadIdx.x]=fmaxf(fmaf(g_a3[o],v,g_c3[o]),0.f);
    }
    __syncthreads();
#pragma unroll
    for(int k=0;k<32;k+=8){
        int o=o0+threadIdx.y+k;
        outf[((size_t)b*128+o)*PP+p0+threadIdx.x]=t[threadIdx.x][threadIdx.y+k];
    }
}

extern "C" void kernel_launch(void* const* d_in, const int* in_sizes, int n_in,
                              void* d_out, int out_size){
    const float* xyz =(const float*)d_in[0];
    const float* feat=(const float*)d_in[1];
    const float* W1  =(const float*)d_in[2];
    const float* g1  =(const float*)d_in[3];
    const float* b1  =(const float*)d_in[4];
    const float* W2  =(const float*)d_in[5];
    const float* g2  =(const float*)d_in[6];
    const float* b2  =(const float*)d_in[7];
    const float* W3  =(const float*)d_in[8];
    const float* g3  =(const float*)d_in[9];
    const float* b3  =(const float*)d_in[10];
    float* out=(float*)d_out;
    float* out_newxyz=out;
    float* out_feat  =out+(size_t)BB*PP*3;

    static int smem_set=0;
    if(!smem_set){
        cudaFuncSetAttribute(gemm_l1, cudaFuncAttributeMaxDynamicSharedMemorySize, SMEM_L12);
        cudaFuncSetAttribute(gemm_l2, cudaFuncAttributeMaxDynamicSharedMemorySize, SMEM_L2T);
        cudaFuncSetAttribute(gemm_l3, cudaFuncAttributeMaxDynamicSharedMemorySize, SMEM_L3T);
        smem_set=1;
    }

    zero_stats<<<1,128>>>();
    {
        dim3 g(NN/32, CC/32, BB), b(32,8);
        transpose_feat<<<g,b>>>(feat);
    }
    {
        dim3 g(NN/256, BB);
        xyz_soa<<<g,256>>>(xyz);
    }
    fps_kernel<<<BB,512>>>(xyz, out_newxyz);
    ballq_kernel<<<(BB*PP)/4,128>>>();
    gemm_l1<<<NROWS/128,512,SMEM_L12>>>(W1);
    mkscale_kernel<<<1,128>>>(g1,b1,1,64);
    gemm_l2<<<NROWS/128,512,SMEM_L2T>>>(W2);
    mkscale_kernel<<<1,128>>>(g2,b2,2,64);
    gemm_l3<<<NROWS/128,512,SMEM_L3T>>>(W3);
    mkscale_kernel<<<1,128>>>(g3,b3,3,128);
    {
        dim3 g(PP/32, 128/32, BB), b(32,8);
        final_kernel<<<g,b>>>(out_feat);
    }
}

// round 12
// speedup vs baseline: 3.7785x; 2.0104x over previous
#include <cuda_runtime.h>
#include <math.h>

#define BB 16
#define NN 4096
#define CC 64
#define PP 1024
#define SS 32
#define NROWS (BB*PP*SS)   // 524288

__device__ float  d_featT[(size_t)BB*NN*CC];
__device__ float  d_xyzT[(size_t)BB*3*NN];
__device__ float  d_newxyz[BB*PP*3];
__device__ int    d_idx[BB*PP*SS];
__device__ float  d_y1[(size_t)NROWS*64];
__device__ float  d_y2[(size_t)NROWS*64];
__device__ float  d_m3[(size_t)BB*PP*128];
__device__ double g_s1[64], g_q1[64], g_s2[64], g_q2[64], g_s3[128], g_q3[128];
__device__ float  g_a1[64], g_c1[64], g_a2[64], g_c2[64], g_a3[128], g_c3[128];

__device__ __forceinline__ float sqdist(float ax,float ay,float az,float bx,float by,float bz){
    float dx=__fsub_rn(ax,bx), dy=__fsub_rn(ay,by), dz=__fsub_rn(az,bz);
    return __fadd_rn(__fadd_rn(__fmul_rn(dx,dx),__fmul_rn(dy,dy)),__fmul_rn(dz,dz));
}
__device__ __forceinline__ unsigned fkey(float f){
    unsigned u=__float_as_uint(f); return (u&0x80000000u)?~u:(u|0x80000000u);
}
__device__ __forceinline__ float finv(unsigned k){
    unsigned u=(k&0x80000000u)?(k&0x7fffffffu):~k; return __uint_as_float(u);
}
__device__ __forceinline__ unsigned long long pk2(float a,float b){
    unsigned long long r; asm("mov.b64 %0,{%1,%2};" : "=l"(r) : "f"(a),"f"(b)); return r;
}
__device__ __forceinline__ void upk2(unsigned long long v,float&a,float&b){
    asm("mov.b64 {%0,%1},%2;" : "=f"(a),"=f"(b) : "l"(v));
}
__device__ __forceinline__ unsigned long long add2(unsigned long long a,unsigned long long b){
    unsigned long long r; asm("add.rn.f32x2 %0,%1,%2;" : "=l"(r) : "l"(a),"l"(b)); return r;
}
__device__ __forceinline__ unsigned long long mul2(unsigned long long a,unsigned long long b){
    unsigned long long r; asm("mul.rn.f32x2 %0,%1,%2;" : "=l"(r) : "l"(a),"l"(b)); return r;
}
__device__ __forceinline__ unsigned f2tf(float f){
    unsigned r; asm("cvt.rna.tf32.f32 %0,%1;" : "=r"(r) : "f"(f)); return r;
}
__device__ __forceinline__ void mma_tf32(float* c, unsigned a0,unsigned a1,unsigned a2,unsigned a3,
                                         unsigned b0,unsigned b1){
    asm("mma.sync.aligned.m16n8k8.row.col.f32.tf32.tf32.f32 "
        "{%0,%1,%2,%3},{%4,%5,%6,%7},{%8,%9},{%0,%1,%2,%3};"
        : "+f"(c[0]),"+f"(c[1]),"+f"(c[2]),"+f"(c[3])
        : "r"(a0),"r"(a1),"r"(a2),"r"(a3),"r"(b0),"r"(b1));
}

__global__ void zero_stats(){
    int t=threadIdx.x;
    if(t<64){g_s1[t]=0.0;g_q1[t]=0.0;g_s2[t]=0.0;g_q2[t]=0.0;}
    if(t<128){g_s3[t]=0.0;g_q3[t]=0.0;}
}

__global__ void transpose_feat(const float* __restrict__ f){
    __shared__ float t[32][33];
    int b=blockIdx.z, c0=blockIdx.y*32, n0=blockIdx.x*32;
    const float* src=f+((size_t)b*CC+c0)*NN+n0;
#pragma unroll
    for(int k=0;k<32;k+=8)
        t[threadIdx.y+k][threadIdx.x]=src[(size_t)(threadIdx.y+k)*NN+threadIdx.x];
    __syncthreads();
    float* dst=d_featT+((size_t)b*NN+n0)*CC+c0;
#pragma unroll
    for(int k=0;k<32;k+=8)
        dst[(size_t)(threadIdx.y+k)*CC+threadIdx.x]=t[threadIdx.x][threadIdx.y+k];
}

__global__ __launch_bounds__(256) void xyz_soa(const float* __restrict__ xyz){
    __shared__ float s[768];
    int b=blockIdx.y, n0=blockIdx.x*256;
    const float* src=xyz+((size_t)b*NN+n0)*3;
    for(int k=threadIdx.x;k<768;k+=256) s[k]=src[k];
    __syncthreads();
    float* dst=d_xyzT+(size_t)b*3*NN;
    int n=n0+threadIdx.x;
    dst[n]      =s[threadIdx.x*3+0];
    dst[NN+n]   =s[threadIdx.x*3+1];
    dst[2*NN+n] =s[threadIdx.x*3+2];
}

__global__ __launch_bounds__(512,1) void fps_kernel(const float* __restrict__ xyz,
                                                    float* __restrict__ out_newxyz){
    int b=blockIdx.x, tid=threadIdx.x;
    int warp=tid>>5, lane=tid&31;
    const float* X=xyz+(size_t)b*NN*3;
    unsigned long long px2[4],py2[4],pz2[4];
    float dd[8];
#pragma unroll
    for(int jj=0;jj<4;jj++){
        int p0=tid+(2*jj)*512, p1=tid+(2*jj+1)*512;
        px2[jj]=pk2(X[p0*3+0],X[p1*3+0]);
        py2[jj]=pk2(X[p0*3+1],X[p1*3+1]);
        pz2[jj]=pk2(X[p0*3+2],X[p1*3+2]);
        dd[2*jj]=1e10f; dd[2*jj+1]=1e10f;
    }
    __shared__ unsigned s_d[2][32];
    __shared__ unsigned s_i[2][32];
    if(tid<32){ s_d[0][tid]=0u; s_d[1][tid]=0u; s_i[0][tid]=0xFFFFFFFFu; s_i[1][tid]=0xFFFFFFFFu; }
    float lx=__ldg(&X[0]), ly=__ldg(&X[1]), lz=__ldg(&X[2]);
    if(tid==0){
        float* o1=d_newxyz+(size_t)b*PP*3; o1[0]=lx;o1[1]=ly;o1[2]=lz;
        float* o2=out_newxyz+(size_t)b*PP*3; o2[0]=lx;o2[1]=ly;o2[2]=lz;
    }
    __syncthreads();
    for(int it=1; it<PP; it++){
        int p=it&1;
        unsigned long long nx=pk2(-lx,-lx), ny=pk2(-ly,-ly), nz=pk2(-lz,-lz);
#pragma unroll
        for(int jj=0;jj<4;jj++){
            unsigned long long dx=add2(px2[jj],nx);
            unsigned long long dy=add2(py2[jj],ny);
            unsigned long long dz=add2(pz2[jj],nz);
            unsigned long long s=add2(add2(mul2(dx,dx),mul2(dy,dy)),mul2(dz,dz));
            float d0,d1; upk2(s,d0,d1);
            dd[2*jj]=fminf(dd[2*jj],d0);
            dd[2*jj+1]=fminf(dd[2*jj+1],d1);
        }
        float m01=fmaxf(dd[0],dd[1]), m23=fmaxf(dd[2],dd[3]);
        float m45=fmaxf(dd[4],dd[5]), m67=fmaxf(dd[6],dd[7]);
        float m=fmaxf(fmaxf(m01,m23),fmaxf(m45,m67));
        unsigned cand=0xFFFFFFFFu;
#pragma unroll
        for(int j=7;j>=0;j--) if(dd[j]==m) cand=tid+(unsigned)(j*512);
        unsigned mb=__float_as_uint(m);
        unsigned wmax=__reduce_max_sync(0xffffffffu, mb);
        unsigned wi=__reduce_min_sync(0xffffffffu, (mb==wmax)?cand:0xFFFFFFFFu);
        if(lane==0){ s_d[p][warp]=wmax; s_i[p][warp]=wi; }
        __syncthreads();
        unsigned dv=s_d[p][lane];
        unsigned bmax=__reduce_max_sync(0xffffffffu, dv);
        unsigned widx=__reduce_min_sync(0xffffffffu, (dv==bmax)?s_i[p][lane]:0xFFFFFFFFu);
        lx=__ldg(&X[widx*3+0]);
        ly=__ldg(&X[widx*3+1]);
        lz=__ldg(&X[widx*3+2]);
        if(tid==0){
            float* o1=d_newxyz+((size_t)b*PP+it)*3; o1[0]=lx;o1[1]=ly;o1[2]=lz;
            float* o2=out_newxyz+((size_t)b*PP+it)*3; o2[0]=lx;o2[1]=ly;o2[2]=lz;
        }
    }
}

__global__ __launch_bounds__(128) void ballq_kernel(){
    int warp=blockIdx.x*4+(threadIdx.x>>5);
    int lane=threadIdx.x&31;
    int b=warp>>10;
    const float* Xx=d_xyzT+(size_t)b*3*NN;
    const float* Xy=Xx+NN;
    const float* Xz=Xx+2*NN;
    float cx=d_newxyz[warp*3+0], cy=d_newxyz[warp*3+1], cz=d_newxyz[warp*3+2];
    int* out=d_idx+(size_t)warp*SS;
    const float R2=0.04f;
    int cnt=0, firstIdx=-1;
    for(int base=0; base<NN && cnt<SS; base+=32){
        int n=base+lane;
        bool in=sqdist(cx,cy,cz,Xx[n],Xy[n],Xz[n])<R2;
        unsigned m=__ballot_sync(0xffffffffu,in);
        if(firstIdx<0 && m) firstIdx=base+__ffs(m)-1;
        if(in){
            int pos=cnt+__popc(m&((1u<<lane)-1u));
            if(pos<SS) out[pos]=n;
        }
        cnt+=__popc(m);
    }
    int written=cnt<SS?cnt:SS;
    if(lane>=written) out[lane]=firstIdx;
}

__global__ void mkscale_kernel(const float* __restrict__ g, const float* __restrict__ bb,
                               int layer, int Cn){
    int o=threadIdx.x;
    if(o>=Cn) return;
    const double inv=1.0/(double)NROWS;
    double s,q;
    if(layer==1){s=g_s1[o];q=g_q1[o];}
    else if(layer==2){s=g_s2[o];q=g_q2[o];}
    else {s=g_s3[o];q=g_q3[o];}
    double m=s*inv, v=q*inv-m*m;
    double aa=(double)g[o]/sqrt(v+1e-5);
    float af=(float)aa, cf=(float)((double)bb[o]-m*aa);
    if(layer==1){g_a1[o]=af;g_c1[o]=cf;}
    else if(layer==2){g_a2[o]=af;g_c2[o]=cf;}
    else {g_a3[o]=af;g_c3[o]=cf;}
}

// smem budgets
#define SMEM_L1T ((128*68 + 128*4 + 64*68 + 64*4 + 128)*4)
#define SMEM_L2T ((128*68 + 64*68 + 128)*4)
#define SMEM_L3T ((128*68 + 128*68 + 256 + 512)*4)

// layer1: tf32 mma over feat K=64 + fp32 xyz-part epilogue; fused gather + stats
__global__ __launch_bounds__(512) void gemm_l1(const float* __restrict__ W1){
    extern __shared__ float dyn[];
    float (*sh_x)[68]=(float(*)[68])dyn;                  // 128 x 64 gathered feat
    float (*sh_d)[4] =(float(*)[4])(dyn+128*68);          // 128 x {dx,dy,dz}
    float (*sh_w)[68]=(float(*)[68])(dyn+128*68+128*4);   // 64 x 64: W1[o][3+k]
    float (*sh_w3)[4]=(float(*)[4])(dyn+128*68+128*4+64*68); // 64 x {w0,w1,w2}
    float* sh_sum=dyn+128*68+128*4+64*68+64*4;
    float* sh_sq =sh_sum+64;
    int tid=threadIdx.x, blk=blockIdx.x;
    for(int e=tid;e<64*67;e+=512){
        int o=e/67, c=e-o*67;
        if(c<3) sh_w3[o][c]=W1[e];
        else    sh_w[o][c-3]=W1[e];
    }
    if(tid<64){ sh_sum[tid]=0.f; sh_sq[tid]=0.f; }
    {
        int r=tid>>2, q=tid&3;
        int grp=blk*4+(r>>5);
        int b=grp>>10;
        int i=d_idx[(size_t)grp*SS+(r&31)];
        const float4* fr=(const float4*)(d_featT+((size_t)b*NN+i)*CC);
        float4* dst=(float4*)&sh_x[r][0];
#pragma unroll
        for(int k=0;k<4;k++) dst[q*4+k]=fr[q*4+k];
        if(q==0){
            const float* xt=d_xyzT+(size_t)b*3*NN;
            const float* cp=d_newxyz+(size_t)grp*3;
            sh_d[r][0]=__fsub_rn(xt[i],      cp[0]);
            sh_d[r][1]=__fsub_rn(xt[NN+i],   cp[1]);
            sh_d[r][2]=__fsub_rn(xt[2*NN+i], cp[2]);
        }
    }
    __syncthreads();
    int w=tid>>5, lane=tid&31, g=lane>>2, t=lane&3;
    int mt=w&7, nh=w>>3;
    int r0=mt*16;
    float acc[4][4];
#pragma unroll
    for(int nt=0;nt<4;nt++){acc[nt][0]=0;acc[nt][1]=0;acc[nt][2]=0;acc[nt][3]=0;}
#pragma unroll
    for(int kt=0;kt<8;kt++){
        int k0=kt*8;
        unsigned a0=f2tf(sh_x[r0+g  ][k0+t  ]);
        unsigned a1=f2tf(sh_x[r0+g+8][k0+t  ]);
        unsigned a2=f2tf(sh_x[r0+g  ][k0+t+4]);
        unsigned a3=f2tf(sh_x[r0+g+8][k0+t+4]);
#pragma unroll
        for(int nt=0;nt<4;nt++){
            int n0=nh*32+nt*8;
            unsigned b0=f2tf(sh_w[n0+g][k0+t  ]);
            unsigned b1=f2tf(sh_w[n0+g][k0+t+4]);
            mma_tf32(acc[nt], a0,a1,a2,a3, b0,b1);
        }
    }
    // fp32 xyz-part epilogue
    float dx0=sh_d[r0+g][0],   dy0=sh_d[r0+g][1],   dz0=sh_d[r0+g][2];
    float dx1=sh_d[r0+g+8][0], dy1=sh_d[r0+g+8][1], dz1=sh_d[r0+g+8][2];
#pragma unroll
    for(int nt=0;nt<4;nt++){
        int n0=nh*32+nt*8;
        int col=n0+2*t;
        float wa0=sh_w3[col][0],   wa1=sh_w3[col][1],   wa2=sh_w3[col][2];
        float wb0=sh_w3[col+1][0], wb1=sh_w3[col+1][1], wb2=sh_w3[col+1][2];
        acc[nt][0]+=dx0*wa0+dy0*wa1+dz0*wa2;
        acc[nt][1]+=dx0*wb0+dy0*wb1+dz0*wb2;
        acc[nt][2]+=dx1*wa0+dy1*wa1+dz1*wa2;
        acc[nt][3]+=dx1*wb0+dy1*wb1+dz1*wb2;
        float2 v0; v0.x=acc[nt][0]; v0.y=acc[nt][1];
        float2 v1; v1.x=acc[nt][2]; v1.y=acc[nt][3];
        *(float2*)(d_y1+((size_t)blk*128+r0+g  )*64+col)=v0;
        *(float2*)(d_y1+((size_t)blk*128+r0+g+8)*64+col)=v1;
        float s0=acc[nt][0]+acc[nt][2], s1=acc[nt][1]+acc[nt][3];
        float q0=acc[nt][0]*acc[nt][0]+acc[nt][2]*acc[nt][2];
        float q1=acc[nt][1]*acc[nt][1]+acc[nt][3]*acc[nt][3];
#pragma unroll
        for(int off=4;off<32;off<<=1){
            s0+=__shfl_xor_sync(0xffffffffu,s0,off);
            s1+=__shfl_xor_sync(0xffffffffu,s1,off);
            q0+=__shfl_xor_sync(0xffffffffu,q0,off);
            q1+=__shfl_xor_sync(0xffffffffu,q1,off);
        }
        if(lane<4){
            atomicAdd(&sh_sum[col],s0); atomicAdd(&sh_sum[col+1],s1);
            atomicAdd(&sh_sq[col],q0);  atomicAdd(&sh_sq[col+1],q1);
        }
    }
    __syncthreads();
    if(tid<64){ atomicAdd(&g_s1[tid],(double)sh_sum[tid]); atomicAdd(&g_q1[tid],(double)sh_sq[tid]); }
}

// layer2: tf32 mma, 512 threads, 128 rows/block; warp = M16 x N32
__global__ __launch_bounds__(512) void gemm_l2(const float* __restrict__ W2){
    extern __shared__ float dyn[];
    float (*sh_x)[68]=(float(*)[68])dyn;
    float (*sh_w)[68]=(float(*)[68])(dyn+128*68);
    float* sh_sum=dyn+128*68+64*68;
    float* sh_sq =sh_sum+64;
    int tid=threadIdx.x, blk=blockIdx.x;
    for(int e=tid;e<64*64;e+=512) sh_w[e>>6][e&63]=W2[e];
    if(tid<64){ sh_sum[tid]=0.f; sh_sq[tid]=0.f; }
    {
        int r=tid>>2, q=tid&3;
        const float4* src=(const float4*)(d_y1+((size_t)blk*128+r)*64+q*16);
#pragma unroll
        for(int k=0;k<4;k++){
            float4 v=src[k];
            int c0=q*16+k*4;
            sh_x[r][c0+0]=fmaxf(fmaf(g_a1[c0+0],v.x,g_c1[c0+0]),0.f);
            sh_x[r][c0+1]=fmaxf(fmaf(g_a1[c0+1],v.y,g_c1[c0+1]),0.f);
            sh_x[r][c0+2]=fmaxf(fmaf(g_a1[c0+2],v.z,g_c1[c0+2]),0.f);
            sh_x[r][c0+3]=fmaxf(fmaf(g_a1[c0+3],v.w,g_c1[c0+3]),0.f);
        }
    }
    __syncthreads();
    int w=tid>>5, lane=tid&31, g=lane>>2, t=lane&3;
    int mt=w&7, nh=w>>3;
    int r0=mt*16;
    float acc[4][4];
#pragma unroll
    for(int nt=0;nt<4;nt++){acc[nt][0]=0;acc[nt][1]=0;acc[nt][2]=0;acc[nt][3]=0;}
#pragma unroll
    for(int kt=0;kt<8;kt++){
        int k0=kt*8;
        unsigned a0=f2tf(sh_x[r0+g  ][k0+t  ]);
        unsigned a1=f2tf(sh_x[r0+g+8][k0+t  ]);
        unsigned a2=f2tf(sh_x[r0+g  ][k0+t+4]);
        unsigned a3=f2tf(sh_x[r0+g+8][k0+t+4]);
#pragma unroll
        for(int nt=0;nt<4;nt++){
            int n0=nh*32+nt*8;
            unsigned b0=f2tf(sh_w[n0+g][k0+t  ]);
            unsigned b1=f2tf(sh_w[n0+g][k0+t+4]);
            mma_tf32(acc[nt], a0,a1,a2,a3, b0,b1);
        }
    }
#pragma unroll
    for(int nt=0;nt<4;nt++){
        int n0=nh*32+nt*8;
        int col=n0+2*t;
        float2 v0; v0.x=acc[nt][0]; v0.y=acc[nt][1];
        float2 v1; v1.x=acc[nt][2]; v1.y=acc[nt][3];
        *(float2*)(d_y2+((size_t)blk*128+r0+g  )*64+col)=v0;
        *(float2*)(d_y2+((size_t)blk*128+r0+g+8)*64+col)=v1;
        float s0=acc[nt][0]+acc[nt][2], s1=acc[nt][1]+acc[nt][3];
        float q0=acc[nt][0]*acc[nt][0]+acc[nt][2]*acc[nt][2];
        float q1=acc[nt][1]*acc[nt][1]+acc[nt][3]*acc[nt][3];
#pragma unroll
        for(int off=4;off<32;off<<=1){
            s0+=__shfl_xor_sync(0xffffffffu,s0,off);
            s1+=__shfl_xor_sync(0xffffffffu,s1,off);
            q0+=__shfl_xor_sync(0xffffffffu,q0,off);
            q1+=__shfl_xor_sync(0xffffffffu,q1,off);
        }
        if(lane<4){
            atomicAdd(&sh_sum[col],s0); atomicAdd(&sh_sum[col+1],s1);
            atomicAdd(&sh_sq[col],q0);  atomicAdd(&sh_sq[col+1],q1);
        }
    }
    __syncthreads();
    if(tid<64){ atomicAdd(&g_s2[tid],(double)sh_sum[tid]); atomicAdd(&g_q2[tid],(double)sh_sq[tid]); }
}

// layer3: tf32 mma, 512 threads, 128 rows (4 pool-groups); warp = M16 x N64
__global__ __launch_bounds__(512) void gemm_l3(const float* __restrict__ W3){
    extern __shared__ float dyn[];
    float (*sh_x)[68]=(float(*)[68])dyn;
    float (*sh_w)[68]=(float(*)[68])(dyn+128*68);
    float* sh_sum=dyn+128*68+128*68;
    float* sh_sq =sh_sum+128;
    unsigned* sh_max=(unsigned*)(sh_sq+128);
    int tid=threadIdx.x, blk=blockIdx.x;
    for(int e=tid;e<128*64;e+=512) sh_w[e>>6][e&63]=W3[e];
    if(tid<128){ sh_sum[tid]=0.f; sh_sq[tid]=0.f; }
    if(tid<512) sh_max[tid]=0u;
    {
        int r=tid>>2, q=tid&3;
        const float4* src=(const float4*)(d_y2+((size_t)blk*128+r)*64+q*16);
#pragma unroll
        for(int k=0;k<4;k++){
            float4 v=src[k];
            int c0=q*16+k*4;
            sh_x[r][c0+0]=fmaxf(fmaf(g_a2[c0+0],v.x,g_c2[c0+0]),0.f);
            sh_x[r][c0+1]=fmaxf(fmaf(g_a2[c0+1],v.y,g_c2[c0+1]),0.f);
            sh_x[r][c0+2]=fmaxf(fmaf(g_a2[c0+2],v.z,g_c2[c0+2]),0.f);
            sh_x[r][c0+3]=fmaxf(fmaf(g_a2[c0+3],v.w,g_c2[c0+3]),0.f);
        }
    }
    __syncthreads();
    int w=tid>>5, lane=tid&31, g=lane>>2, t=lane&3;
    int mt=w&7, nh=w>>3;
    int r0=mt*16;
    int grp=mt>>1;
    float acc[8][4];
#pragma unroll
    for(int nt=0;nt<8;nt++){acc[nt][0]=0;acc[nt][1]=0;acc[nt][2]=0;acc[nt][3]=0;}
#pragma unroll
    for(int kt=0;kt<8;kt++){
        int k0=kt*8;
        unsigned a0=f2tf(sh_x[r0+g  ][k0+t  ]);
        unsigned a1=f2tf(sh_x[r0+g+8][k0+t  ]);
        unsigned a2=f2tf(sh_x[r0+g  ][k0+t+4]);
        unsigned a3=f2tf(sh_x[r0+g+8][k0+t+4]);
#pragma unroll
        for(int nt=0;nt<8;nt++){
            int n0=nh*64+nt*8;
            unsigned b0=f2tf(sh_w[n0+g][k0+t  ]);
            unsigned b1=f2tf(sh_w[n0+g][k0+t+4]);
            mma_tf32(acc[nt], a0,a1,a2,a3, b0,b1);
        }
    }
#pragma unroll
    for(int nt=0;nt<8;nt++){
        int n0=nh*64+nt*8;
        int col=n0+2*t;
        float s0=acc[nt][0]+acc[nt][2], s1=acc[nt][1]+acc[nt][3];
        float q0=acc[nt][0]*acc[nt][0]+acc[nt][2]*acc[nt][2];
        float q1=acc[nt][1]*acc[nt][1]+acc[nt][3]*acc[nt][3];
        float m0=fmaxf(acc[nt][0],acc[nt][2]), m1=fmaxf(acc[nt][1],acc[nt][3]);
#pragma unroll
        for(int off=4;off<32;off<<=1){
            s0+=__shfl_xor_sync(0xffffffffu,s0,off);
            s1+=__shfl_xor_sync(0xffffffffu,s1,off);
            q0+=__shfl_xor_sync(0xffffffffu,q0,off);
            q1+=__shfl_xor_sync(0xffffffffu,q1,off);
            m0=fmaxf(m0,__shfl_xor_sync(0xffffffffu,m0,off));
            m1=fmaxf(m1,__shfl_xor_sync(0xffffffffu,m1,off));
        }
        if(lane<4){
            atomicAdd(&sh_sum[col],s0); atomicAdd(&sh_sum[col+1],s1);
            atomicAdd(&sh_sq[col],q0);  atomicAdd(&sh_sq[col+1],q1);
            atomicMax(&sh_max[grp*128+col],fkey(m0));
            atomicMax(&sh_max[grp*128+col+1],fkey(m1));
        }
    }
    __syncthreads();
    if(tid<128){
        atomicAdd(&g_s3[tid],(double)sh_sum[tid]);
        atomicAdd(&g_q3[tid],(double)sh_sq[tid]);
    }
    if(tid<512)
        d_m3[((size_t)blk*4+(tid>>7))*128+(tid&127)]=finv(sh_max[tid]);
}

__global__ void final_kernel(float* __restrict__ outf){
    __shared__ float t[32][33];
    int b=blockIdx.z, o0=blockIdx.y*32, p0=blockIdx.x*32;
#pragma unroll
    for(int k=0;k<32;k+=8){
        int p=p0+threadIdx.y+k, o=o0+threadIdx.x;
        float v=d_m3[((size_t)b*PP+p)*128+o];
        t[threadIdx.y+k][threadIdx.x]=fmaxf(fmaf(g_a3[o],v,g_c3[o]),0.f);
    }
    __syncthreads();
#pragma unroll
    for(int k=0;k<32;k+=8){
        int o=o0+threadIdx.y+k;
        outf[((size_t)b*128+o)*PP+p0+threadIdx.x]=t[threadIdx.x][threadIdx.y+k];
    }
}

extern "C" void kernel_launch(void* const* d_in, const int* in_sizes, int n_in,
                              void* d_out, int out_size){
    const float* xyz =(const float*)d_in[0];
    const float* feat=(const float*)d_in[1];
    const float* W1  =(const float*)d_in[2];
    const float* g1  =(const float*)d_in[3];
    const float* b1  =(const float*)d_in[4];
    const float* W2  =(const float*)d_in[5];
    const float* g2  =(const float*)d_in[6];
    const float* b2  =(const float*)d_in[7];
    const float* W3  =(const float*)d_in[8];
    const float* g3  =(const float*)d_in[9];
    const float* b3  =(const float*)d_in[10];
    float* out=(float*)d_out;
    float* out_newxyz=out;
    float* out_feat  =out+(size_t)BB*PP*3;

    static int smem_set=0;
    if(!smem_set){
        cudaFuncSetAttribute(gemm_l1, cudaFuncAttributeMaxDynamicSharedMemorySize, SMEM_L1T);
        cudaFuncSetAttribute(gemm_l2, cudaFuncAttributeMaxDynamicSharedMemorySize, SMEM_L2T);
        cudaFuncSetAttribute(gemm_l3, cudaFuncAttributeMaxDynamicSharedMemorySize, SMEM_L3T);
        smem_set=1;
    }

    zero_stats<<<1,128>>>();
    {
        dim3 g(NN/32, CC/32, BB), b(32,8);
        transpose_feat<<<g,b>>>(feat);
    }
    {
        dim3 g(NN/256, BB);
        xyz_soa<<<g,256>>>(xyz);
    }
    fps_kernel<<<BB,512>>>(xyz, out_newxyz);
    ballq_kernel<<<(BB*PP)/4,128>>>();
    gemm_l1<<<NROWS/128,512,SMEM_L1T>>>(W1);
    mkscale_kernel<<<1,128>>>(g1,b1,1,64);
    gemm_l2<<<NROWS/128,512,SMEM_L2T>>>(W2);
    mkscale_kernel<<<1,128>>>(g2,b2,2,64);
    gemm_l3<<<NROWS/128,512,SMEM_L3T>>>(W3);
    mkscale_kernel<<<1,128>>>(g3,b3,3,128);
    {
        dim3 g(PP/32, 128/32, BB), b(32,8);
        final_kernel<<<g,b>>>(out_feat);
    }
}